// round 6
// baseline (speedup 1.0000x reference)
#include <cuda_runtime.h>
#include <math.h>
#include <stdint.h>

// Problem constants
#define BB    8
#define SAQ   512
#define SBK   512
#define EDIM  1024
#define HH    16
#define DH    64
#define FFD   4096
#define LL    9
#define NTOK  (BB*SAQ)          // 4096 rows
#define WEIGHTV 5.0f
#define EPSV    1e-5f
#define ATT_SCALE 0.125f        // 1/sqrt(64)

// ---------------- scratch (device globals; no allocation allowed) ------------
__device__ float g_bufA [NTOK*EDIM];
__device__ float g_bufQ [NTOK*EDIM];
__device__ float g_bufK [NTOK*EDIM];
__device__ float g_bufV [NTOK*EDIM];
__device__ float g_bufC [NTOK*EDIM];
__device__ float g_bufO [NTOK*EDIM];
__device__ float g_bufA1[NTOK*EDIM];
__device__ float g_bufS [(size_t)BB*HH*SAQ*SBK];   // 33.5M floats
__device__ float g_bufH [(size_t)NTOK*FFD];        // 16.7M floats
__device__ float g_partials[64];                   // 32 blocks x (wce, valid)

// ---------------- tf32 helpers ----------------------------------------------
__device__ __forceinline__ void split_tf32(float x, float& hi, float& lo) {
    uint32_t h;
    asm("cvt.rna.tf32.f32 %0, %1;" : "=r"(h) : "f"(x));
    hi = __uint_as_float(h);
    float r = x - hi;
    uint32_t l;
    asm("cvt.rna.tf32.f32 %0, %1;" : "=r"(l) : "f"(r));
    lo = __uint_as_float(l);
}

// m16n8k8 tf32 mma: D = A*B + D (fp32 accum)
#define MMA_TF32(c, a, b) \
    asm("mma.sync.aligned.m16n8k8.row.col.f32.tf32.tf32.f32 " \
        "{%0,%1,%2,%3}, {%4,%5,%6,%7}, {%8,%9}, {%0,%1,%2,%3};" \
        : "+f"((c)[0]), "+f"((c)[1]), "+f"((c)[2]), "+f"((c)[3]) \
        : "r"((a)[0]), "r"((a)[1]), "r"((a)[2]), "r"((a)[3]), \
          "r"((b)[0]), "r"((b)[1]))

// ========== tensor-core GEMM: C[M,N] = A[M,K] @ W[N,K]^T + bias, opt relu ====
// 3xTF32 split. CTA tile 128x128, 256 threads = 8 warps (4x2), warp 32x64.
// Smem [k][m] with pad 132 -> conflict-free m16n8k8 fragment loads.
#define KC 16
#define PADW 132

__global__ void __launch_bounds__(256, 1)
gemm_mma_kernel(const float* __restrict__ A, const float* __restrict__ W,
                const float* __restrict__ bias, float* __restrict__ C,
                int M, int N, int K, int relu)
{
    __shared__ float As_hi[KC][PADW], As_lo[KC][PADW];
    __shared__ float Ws_hi[KC][PADW], Ws_lo[KC][PADW];

    const int tid  = threadIdx.x;
    const int wid  = tid >> 5;
    const int lane = tid & 31;
    const int wm   = wid >> 1;          // 0..3 warp row (32 rows each)
    const int wn   = wid & 1;           // 0..1 warp col (64 cols each)
    const int gr   = lane >> 2;         // 0..7
    const int gc   = lane & 3;          // 0..3
    const int bx = blockIdx.x, by = blockIdx.y;

    const float* Ab = A + (size_t)(by * 128) * K;
    const float* Wb = W + (size_t)(bx * 128) * K;

    float acc[2][8][4];
#pragma unroll
    for (int mi = 0; mi < 2; mi++)
#pragma unroll
        for (int ni = 0; ni < 8; ni++)
#pragma unroll
            for (int r = 0; r < 4; r++) acc[mi][ni][r] = 0.f;

    // staging: thread covers (row0,kq4) and (row1,kq4)
    const int row0 = tid >> 2;          // 0..63
    const int row1 = row0 + 64;
    const int kq4  = (tid & 3) << 2;    // 0,4,8,12

    float4 pa0 = *(const float4*)(Ab + (size_t)row0 * K + kq4);
    float4 pa1 = *(const float4*)(Ab + (size_t)row1 * K + kq4);
    float4 pw0 = *(const float4*)(Wb + (size_t)row0 * K + kq4);
    float4 pw1 = *(const float4*)(Wb + (size_t)row1 * K + kq4);

    for (int kt = 0; kt < K; kt += KC) {
        // ---- split + store to smem ----
        {
            float h, l;
            const float* va;
            va = &pa0.x;
#pragma unroll
            for (int j = 0; j < 4; j++) {
                split_tf32(va[j], h, l);
                As_hi[kq4 + j][row0] = h; As_lo[kq4 + j][row0] = l;
            }
            va = &pa1.x;
#pragma unroll
            for (int j = 0; j < 4; j++) {
                split_tf32(va[j], h, l);
                As_hi[kq4 + j][row1] = h; As_lo[kq4 + j][row1] = l;
            }
            va = &pw0.x;
#pragma unroll
            for (int j = 0; j < 4; j++) {
                split_tf32(va[j], h, l);
                Ws_hi[kq4 + j][row0] = h; Ws_lo[kq4 + j][row0] = l;
            }
            va = &pw1.x;
#pragma unroll
            for (int j = 0; j < 4; j++) {
                split_tf32(va[j], h, l);
                Ws_hi[kq4 + j][row1] = h; Ws_lo[kq4 + j][row1] = l;
            }
        }
        __syncthreads();

        // ---- prefetch next chunk (latency hidden by compute below) ----
        if (kt + KC < K) {
            const int ko = kt + KC + kq4;
            pa0 = *(const float4*)(Ab + (size_t)row0 * K + ko);
            pa1 = *(const float4*)(Ab + (size_t)row1 * K + ko);
            pw0 = *(const float4*)(Wb + (size_t)row0 * K + ko);
            pw1 = *(const float4*)(Wb + (size_t)row1 * K + ko);
        }

        // ---- compute: 2 k8 steps ----
#pragma unroll
        for (int kq = 0; kq < KC; kq += 8) {
            uint32_t ah[2][4], al[2][4];
#pragma unroll
            for (int mi = 0; mi < 2; mi++) {
                const int m0 = wm * 32 + mi * 16;
                ah[mi][0] = __float_as_uint(As_hi[kq + gc    ][m0 + gr    ]);
                ah[mi][1] = __float_as_uint(As_hi[kq + gc    ][m0 + gr + 8]);
                ah[mi][2] = __float_as_uint(As_hi[kq + gc + 4][m0 + gr    ]);
                ah[mi][3] = __float_as_uint(As_hi[kq + gc + 4][m0 + gr + 8]);
                al[mi][0] = __float_as_uint(As_lo[kq + gc    ][m0 + gr    ]);
                al[mi][1] = __float_as_uint(As_lo[kq + gc    ][m0 + gr + 8]);
                al[mi][2] = __float_as_uint(As_lo[kq + gc + 4][m0 + gr    ]);
                al[mi][3] = __float_as_uint(As_lo[kq + gc + 4][m0 + gr + 8]);
            }
            uint32_t bh[8][2], bl[8][2];
#pragma unroll
            for (int ni = 0; ni < 8; ni++) {
                const int n0 = wn * 64 + ni * 8;
                bh[ni][0] = __float_as_uint(Ws_hi[kq + gc    ][n0 + gr]);
                bh[ni][1] = __float_as_uint(Ws_hi[kq + gc + 4][n0 + gr]);
                bl[ni][0] = __float_as_uint(Ws_lo[kq + gc    ][n0 + gr]);
                bl[ni][1] = __float_as_uint(Ws_lo[kq + gc + 4][n0 + gr]);
            }
#pragma unroll
            for (int mi = 0; mi < 2; mi++)
#pragma unroll
                for (int ni = 0; ni < 8; ni++) {
                    MMA_TF32(acc[mi][ni], ah[mi], bh[ni]);
                    MMA_TF32(acc[mi][ni], ah[mi], bl[ni]);
                    MMA_TF32(acc[mi][ni], al[mi], bh[ni]);
                }
        }
        __syncthreads();
    }

    // ---- epilogue: c0/c1 at (row gr, col gc*2 / +1); c2/c3 at row gr+8 ----
#pragma unroll
    for (int mi = 0; mi < 2; mi++) {
        const int r0 = by * 128 + wm * 32 + mi * 16 + gr;
#pragma unroll
        for (int ni = 0; ni < 8; ni++) {
            const int c = bx * 128 + wn * 64 + ni * 8 + gc * 2;
            const float b0 = bias[c], b1 = bias[c + 1];
            float2 o0, o1;
            o0.x = acc[mi][ni][0] + b0; o0.y = acc[mi][ni][1] + b1;
            o1.x = acc[mi][ni][2] + b0; o1.y = acc[mi][ni][3] + b1;
            if (relu) {
                o0.x = fmaxf(o0.x, 0.f); o0.y = fmaxf(o0.y, 0.f);
                o1.x = fmaxf(o1.x, 0.f); o1.y = fmaxf(o1.y, 0.f);
            }
            *(float2*)(C + (size_t)r0 * N + c)       = o0;
            *(float2*)(C + (size_t)(r0 + 8) * N + c) = o1;
        }
    }
}

// ---------------- attention scores: S[b,h,q,k] = scale * Q.Kh^T -------------
__global__ void __launch_bounds__(256)
attn_scores_kernel(const float* __restrict__ Q, const float* __restrict__ Km,
                   float* __restrict__ S)
{
    int z = blockIdx.z;                 // b*H + h
    int b = z >> 4, h = z & 15;
    const float* Qp = Q + (size_t)b * SAQ * EDIM + h * DH;
    const float* Kp = Km + (size_t)b * SBK * EDIM + h * DH;
    float* Sp = S + (size_t)z * SAQ * SBK;
    int q0 = blockIdx.y * 64, k0 = blockIdx.x * 64;
    int tid = threadIdx.x, tx = tid & 15, ty = tid >> 4;

    __shared__ float Qs[64][64];  // [d][q]
    __shared__ float Ks[64][64];  // [d][k]

#pragma unroll
    for (int i = 0; i < 4; i++) {
        int f = tid + i * 256;          // 0..1023
        int row = f >> 4;               // 0..63
        int dq  = (f & 15) << 2;        // 0..60
        float4 a = *(const float4*)(Qp + (size_t)(q0 + row) * EDIM + dq);
        Qs[dq+0][row] = a.x; Qs[dq+1][row] = a.y;
        Qs[dq+2][row] = a.z; Qs[dq+3][row] = a.w;
        float4 k = *(const float4*)(Kp + (size_t)(k0 + row) * EDIM + dq);
        Ks[dq+0][row] = k.x; Ks[dq+1][row] = k.y;
        Ks[dq+2][row] = k.z; Ks[dq+3][row] = k.w;
    }
    __syncthreads();

    float acc[4][4];
#pragma unroll
    for (int i = 0; i < 4; i++)
#pragma unroll
        for (int j = 0; j < 4; j++) acc[i][j] = 0.f;

#pragma unroll
    for (int d = 0; d < 64; d++) {
        float4 a = *(const float4*)&Qs[d][ty*4];
        float4 b2 = *(const float4*)&Ks[d][tx*4];
        float av[4] = {a.x,a.y,a.z,a.w};
        float bv[4] = {b2.x,b2.y,b2.z,b2.w};
#pragma unroll
        for (int i = 0; i < 4; i++)
#pragma unroll
            for (int j = 0; j < 4; j++)
                acc[i][j] += av[i] * bv[j];
    }

#pragma unroll
    for (int i = 0; i < 4; i++) {
        float4 v;
        v.x = acc[i][0] * ATT_SCALE; v.y = acc[i][1] * ATT_SCALE;
        v.z = acc[i][2] * ATT_SCALE; v.w = acc[i][3] * ATT_SCALE;
        *(float4*)(Sp + (size_t)(q0 + ty*4 + i) * SBK + k0 + tx*4) = v;
    }
}

// ---------------- row softmax over last dim (512) ---------------------------
__global__ void __launch_bounds__(128)
softmax_kernel(float* __restrict__ S)
{
    size_t row = blockIdx.x;
    float* p = S + row * SBK;
    int tid = threadIdx.x;
    __shared__ float sbuf[4];

    float4 v = ((float4*)p)[tid];
    float m = fmaxf(fmaxf(v.x, v.y), fmaxf(v.z, v.w));
#pragma unroll
    for (int o = 16; o > 0; o >>= 1) m = fmaxf(m, __shfl_xor_sync(0xffffffffu, m, o));
    if ((tid & 31) == 0) sbuf[tid >> 5] = m;
    __syncthreads();
    m = fmaxf(fmaxf(sbuf[0], sbuf[1]), fmaxf(sbuf[2], sbuf[3]));
    __syncthreads();

    float4 e;
    e.x = expf(v.x - m); e.y = expf(v.y - m);
    e.z = expf(v.z - m); e.w = expf(v.w - m);
    float s = e.x + e.y + e.z + e.w;
#pragma unroll
    for (int o = 16; o > 0; o >>= 1) s += __shfl_xor_sync(0xffffffffu, s, o);
    if ((tid & 31) == 0) sbuf[tid >> 5] = s;
    __syncthreads();
    s = sbuf[0] + sbuf[1] + sbuf[2] + sbuf[3];
    float inv = 1.0f / s;
    e.x *= inv; e.y *= inv; e.z *= inv; e.w *= inv;
    ((float4*)p)[tid] = e;
}

// ---------------- ctx[b,q,h*64+d] = sum_k P[z,q,k] * V[b,k,h*64+d] ----------
__global__ void __launch_bounds__(256)
attn_ctx_kernel(const float* __restrict__ P, const float* __restrict__ V,
                float* __restrict__ Ctx)
{
    int z = blockIdx.z;
    int b = z >> 4, h = z & 15;
    const float* Pp = P + (size_t)z * SAQ * SBK;
    const float* Vp = V + (size_t)b * SBK * EDIM + h * DH;
    float* Cp = Ctx + (size_t)b * SAQ * EDIM + h * DH;
    int q0 = blockIdx.y * 64;
    int tid = threadIdx.x, tx = tid & 15, ty = tid >> 4;

    __shared__ float Ps[32][64];  // [k][q]
    __shared__ float Vs[32][64];  // [k][d]

    float acc[4][4];
#pragma unroll
    for (int i = 0; i < 4; i++)
#pragma unroll
        for (int j = 0; j < 4; j++) acc[i][j] = 0.f;

    for (int kt = 0; kt < SBK; kt += 32) {
#pragma unroll
        for (int i = 0; i < 2; i++) {
            int f = tid + i * 256;        // 0..511
            {   // P tile: 64 q rows x 32 k cols
                int row = f >> 3;         // 0..63
                int kq  = (f & 7) << 2;   // 0..28
                float4 p = *(const float4*)(Pp + (size_t)(q0 + row) * SBK + kt + kq);
                Ps[kq+0][row] = p.x; Ps[kq+1][row] = p.y;
                Ps[kq+2][row] = p.z; Ps[kq+3][row] = p.w;
            }
            {   // V tile: 32 k rows x 64 d cols
                int row = f >> 4;         // 0..31
                int dq  = (f & 15) << 2;  // 0..60
                float4 vv = *(const float4*)(Vp + (size_t)(kt + row) * EDIM + dq);
                *(float4*)&Vs[row][dq] = vv;
            }
        }
        __syncthreads();

#pragma unroll
        for (int kk = 0; kk < 32; kk++) {
            float4 a = *(const float4*)&Ps[kk][ty*4];
            float4 b2 = *(const float4*)&Vs[kk][tx*4];
            float av[4] = {a.x,a.y,a.z,a.w};
            float bv[4] = {b2.x,b2.y,b2.z,b2.w};
#pragma unroll
            for (int i = 0; i < 4; i++)
#pragma unroll
                for (int j = 0; j < 4; j++)
                    acc[i][j] += av[i] * bv[j];
        }
        __syncthreads();
    }

#pragma unroll
    for (int i = 0; i < 4; i++) {
        float4 v;
        v.x = acc[i][0]; v.y = acc[i][1]; v.z = acc[i][2]; v.w = acc[i][3];
        *(float4*)(Cp + (size_t)(q0 + ty*4 + i) * EDIM + tx*4) = v;
    }
}

// ---------------- LayerNorm(residual): Y = LN(X + R) * g + b ----------------
__global__ void __launch_bounds__(256)
ln_residual_kernel(const float* __restrict__ X, const float* __restrict__ R,
                   const float* __restrict__ g, const float* __restrict__ bta,
                   float* __restrict__ Y)
{
    int row = blockIdx.x;
    int tid = threadIdx.x;                // 256 threads, 4 floats each
    __shared__ float sbuf[8];

    float4 x = ((const float4*)(X + (size_t)row * EDIM))[tid];
    float4 r = ((const float4*)(R + (size_t)row * EDIM))[tid];
    float4 v;
    v.x = x.x + r.x; v.y = x.y + r.y; v.z = x.z + r.z; v.w = x.w + r.w;

    float s = v.x + v.y + v.z + v.w;
#pragma unroll
    for (int o = 16; o > 0; o >>= 1) s += __shfl_xor_sync(0xffffffffu, s, o);
    if ((tid & 31) == 0) sbuf[tid >> 5] = s;
    __syncthreads();
    if (tid < 32) {
        float t = (tid < 8) ? sbuf[tid] : 0.f;
#pragma unroll
        for (int o = 4; o > 0; o >>= 1) t += __shfl_xor_sync(0xffffffffu, t, o);
        if (tid == 0) sbuf[0] = t;
    }
    __syncthreads();
    float mean = sbuf[0] * (1.0f / EDIM);
    __syncthreads();

    float4 d;
    d.x = v.x - mean; d.y = v.y - mean; d.z = v.z - mean; d.w = v.w - mean;
    float sq = d.x*d.x + d.y*d.y + d.z*d.z + d.w*d.w;
#pragma unroll
    for (int o = 16; o > 0; o >>= 1) sq += __shfl_xor_sync(0xffffffffu, sq, o);
    if ((tid & 31) == 0) sbuf[tid >> 5] = sq;
    __syncthreads();
    if (tid < 32) {
        float t = (tid < 8) ? sbuf[tid] : 0.f;
#pragma unroll
        for (int o = 4; o > 0; o >>= 1) t += __shfl_xor_sync(0xffffffffu, t, o);
        if (tid == 0) sbuf[0] = t;
    }
    __syncthreads();
    float var = sbuf[0] * (1.0f / EDIM);
    float inv = rsqrtf(var + EPSV);

    float4 gg = ((const float4*)g)[tid];
    float4 bb = ((const float4*)bta)[tid];
    float4 o4;
    o4.x = d.x * inv * gg.x + bb.x;
    o4.y = d.y * inv * gg.y + bb.y;
    o4.z = d.z * inv * gg.z + bb.z;
    o4.w = d.w * inv * gg.w + bb.w;
    ((float4*)(Y + (size_t)row * EDIM))[tid] = o4;
}

// ---------------- classifier + per-row loss + predicted labels --------------
__global__ void __launch_bounds__(128)
cls_kernel(const float* __restrict__ A, const float* __restrict__ cw,
           const float* __restrict__ cb, const int* __restrict__ mask,
           const int* __restrict__ cand, const int* __restrict__ labels,
           float* __restrict__ out_lab_f, int* __restrict__ out_lab_i,
           int write_float, float* __restrict__ partials)
{
    __shared__ float w0[EDIM];
    __shared__ float w1[EDIM];
    __shared__ float red[128];
    int tid = threadIdx.x;
#pragma unroll
    for (int i = 0; i < EDIM / 128; i++) {
        w0[tid + i * 128] = cw[tid + i * 128];
        w1[tid + i * 128] = cw[EDIM + tid + i * 128];
    }
    __syncthreads();

    int row = blockIdx.x * 128 + tid;     // 0..4095
    const float* a = A + (size_t)row * EDIM;
    float e0 = cb[0], e1 = cb[1];
#pragma unroll 4
    for (int i = 0; i < EDIM; i += 4) {
        float4 av = *(const float4*)(a + i);
        e0 += av.x * w0[i] + av.y * w0[i+1] + av.z * w0[i+2] + av.w * w0[i+3];
        e1 += av.x * w1[i] + av.y * w1[i+1] + av.z * w1[i+2] + av.w * w1[i+3];
    }
    int lab = labels[row];
    float m = fmaxf(e0, e1);
    float lse = m + logf(expf(e0 - m) + expf(e1 - m));
    float logp = ((lab == 1) ? e1 : e0) - lse;
    float ce = -logp;
    float w = (lab == 1) ? WEIGHTV : 1.0f;
    float valid = (mask[row] == 1) ? 1.0f : 0.0f;
    float contrib = ce * w * valid;

    int pred = (e1 > e0) ? 1 : 0;        // jnp.argmax: ties -> 0
    int pl = (cand[row] == 1 && pred == 1) ? 1 : 0;
    if (write_float) out_lab_f[row] = (float)pl;
    else             out_lab_i[row] = pl;

    // deterministic block reduce of (contrib, valid)
    red[tid] = contrib;
    __syncthreads();
    for (int o = 64; o > 0; o >>= 1) {
        if (tid < o) red[tid] += red[tid + o];
        __syncthreads();
    }
    if (tid == 0) partials[2 * blockIdx.x] = red[0];
    __syncthreads();
    red[tid] = valid;
    __syncthreads();
    for (int o = 64; o > 0; o >>= 1) {
        if (tid < o) red[tid] += red[tid + o];
        __syncthreads();
    }
    if (tid == 0) partials[2 * blockIdx.x + 1] = red[0];
}

__global__ void finalize_kernel(const float* __restrict__ partials, int nblocks,
                                float* __restrict__ out_loss, int write_float)
{
    if (threadIdx.x == 0 && write_float) {
        float s = 0.f, v = 0.f;
        for (int i = 0; i < nblocks; i++) { s += partials[2*i]; v += partials[2*i+1]; }
        out_loss[0] = s / fmaxf(v, 1.0f);
    }
}

// ---------------------------- host driver -----------------------------------
extern "C" void kernel_launch(void* const* d_in, const int* in_sizes, int n_in,
                              void* d_out, int out_size)
{
    const float* enc   = (const float*)d_in[0];
    const float* desc  = (const float*)d_in[1];
    const int*   maskA = (const int*)  d_in[2];
    const int*   cand  = (const int*)  d_in[3];
    const int*   labels= (const int*)  d_in[4];
    const float* ipw   = (const float*)d_in[5];   // (L, 3E, E)
    const float* ipb   = (const float*)d_in[6];   // (L, 3E)
    const float* outw  = (const float*)d_in[7];   // (L, E, E)
    const float* outb  = (const float*)d_in[8];   // (L, E)
    const float* ln1g  = (const float*)d_in[9];
    const float* ln1b  = (const float*)d_in[10];
    const float* fw1   = (const float*)d_in[11];  // (L, F, E)
    const float* fb1   = (const float*)d_in[12];  // (L, F)
    const float* fw2   = (const float*)d_in[13];  // (L, E, F)
    const float* fb2   = (const float*)d_in[14];  // (L, E)
    const float* ln2g  = (const float*)d_in[15];
    const float* ln2b  = (const float*)d_in[16];
    const float* clsw  = (const float*)d_in[17];  // (C, E)
    const float* clsb  = (const float*)d_in[18];  // (C,)

    float *pA, *pQ, *pK, *pV, *pC, *pO, *pA1, *pS, *pH, *pPart;
    cudaGetSymbolAddress((void**)&pA,  g_bufA);
    cudaGetSymbolAddress((void**)&pQ,  g_bufQ);
    cudaGetSymbolAddress((void**)&pK,  g_bufK);
    cudaGetSymbolAddress((void**)&pV,  g_bufV);
    cudaGetSymbolAddress((void**)&pC,  g_bufC);
    cudaGetSymbolAddress((void**)&pO,  g_bufO);
    cudaGetSymbolAddress((void**)&pA1, g_bufA1);
    cudaGetSymbolAddress((void**)&pS,  g_bufS);
    cudaGetSymbolAddress((void**)&pH,  g_bufH);
    cudaGetSymbolAddress((void**)&pPart, g_partials);

    // zero out output (poisoned with 0xAA by harness)
    cudaMemsetAsync(d_out, 0, (size_t)out_size * sizeof(float));

    // A <- encoded_matrix
    cudaMemcpyAsync(pA, enc, (size_t)NTOK * EDIM * sizeof(float),
                    cudaMemcpyDeviceToDevice);

    const dim3 gemm_tb(256);
    const dim3 g_proj(EDIM / 128, NTOK / 128);         // (8, 32)
    const dim3 g_ffn1(FFD / 128, NTOK / 128);          // (32, 32)
    const dim3 g_sc(SBK / 64, SAQ / 64, BB * HH);      // (8, 8, 128)
    const dim3 g_ctx(1, SAQ / 64, BB * HH);            // (1, 8, 128)

    for (int l = 0; l < LL; l++) {
        const float* wq = ipw + (size_t)l * 3 * EDIM * EDIM;
        const float* wk = wq + (size_t)EDIM * EDIM;
        const float* wv = wk + (size_t)EDIM * EDIM;
        const float* bq = ipb + (size_t)l * 3 * EDIM;
        const float* bk = bq + EDIM;
        const float* bv = bk + EDIM;

        gemm_mma_kernel<<<g_proj, gemm_tb>>>(pA,   wq, bq, pQ, NTOK, EDIM, EDIM, 0);
        gemm_mma_kernel<<<g_proj, gemm_tb>>>(desc, wk, bk, pK, NTOK, EDIM, EDIM, 0);
        gemm_mma_kernel<<<g_proj, gemm_tb>>>(desc, wv, bv, pV, NTOK, EDIM, EDIM, 0);

        attn_scores_kernel<<<g_sc, 256>>>(pQ, pK, pS);
        softmax_kernel<<<BB * HH * SAQ, 128>>>(pS);
        attn_ctx_kernel<<<g_ctx, 256>>>(pS, pV, pC);

        gemm_mma_kernel<<<g_proj, gemm_tb>>>(pC, outw + (size_t)l * EDIM * EDIM,
                                             outb + (size_t)l * EDIM, pO,
                                             NTOK, EDIM, EDIM, 0);

        ln_residual_kernel<<<NTOK, 256>>>(pA, pO, ln1g + (size_t)l * EDIM,
                                          ln1b + (size_t)l * EDIM, pA1);

        gemm_mma_kernel<<<g_ffn1, gemm_tb>>>(pA1, fw1 + (size_t)l * FFD * EDIM,
                                             fb1 + (size_t)l * FFD, pH,
                                             NTOK, FFD, EDIM, 1);
        gemm_mma_kernel<<<g_proj, gemm_tb>>>(pH, fw2 + (size_t)l * EDIM * FFD,
                                             fb2 + (size_t)l * EDIM, pO,
                                             NTOK, EDIM, FFD, 0);

        ln_residual_kernel<<<NTOK, 256>>>(pA1, pO, ln2g + (size_t)l * EDIM,
                                          ln2b + (size_t)l * EDIM, pA);
    }

    int write_float = (out_size > NTOK) ? 1 : 0;
    int lab_off = write_float ? (out_size - NTOK) : 0;
    float* outf = (float*)d_out;
    int*   outi = (int*)d_out;

    cls_kernel<<<NTOK / 128, 128>>>(pA, clsw, clsb, maskA, cand, labels,
                                    outf + lab_off, outi, write_float, pPart);
    finalize_kernel<<<1, 32>>>(pPart, NTOK / 128, outf, write_float);
}

// round 7
// speedup vs baseline: 1.7371x; 1.7371x over previous
#include <cuda_runtime.h>
#include <cuda_fp16.h>
#include <math.h>
#include <stdint.h>

// Problem constants
#define BB    8
#define SAQ   512
#define SBK   512
#define EDIM  1024
#define HH    16
#define DH    64
#define FFD   4096
#define LL    9
#define NTOK  (BB*SAQ)          // 4096 rows
#define WEIGHTV 5.0f
#define EPSV    1e-5f
#define ATT_SCALE 0.125f        // 1/sqrt(64)
#define KVSTR 2048              // fused K|V row stride

// ---------------- scratch (device globals; no allocation allowed) ------------
__device__ float g_bufA [NTOK*EDIM];
__device__ float g_bufQ [NTOK*EDIM];
__device__ float g_bufKV[NTOK*KVSTR];              // [row][0:1024]=K, [1024:2048]=V
__device__ float g_bufC [NTOK*EDIM];
__device__ float g_bufO [NTOK*EDIM];
__device__ float g_bufA1[NTOK*EDIM];
__device__ float g_bufS [(size_t)BB*HH*SAQ*SBK];   // 33.5M floats
__device__ float g_bufH [(size_t)NTOK*FFD];        // 16.7M floats
__device__ float g_partials[64];

// ---------------- fp16 split helpers -----------------------------------------
__device__ __forceinline__ void split_h2(float x, float y,
                                         uint32_t& hi, uint32_t& lo) {
    __half hx = __float2half_rn(x), hy = __float2half_rn(y);
    __half lx = __float2half_rn(x - __half2float(hx));
    __half ly = __float2half_rn(y - __half2float(hy));
    __half2 vh = __halves2half2(hx, hy);
    __half2 vl = __halves2half2(lx, ly);
    hi = *(uint32_t*)&vh;
    lo = *(uint32_t*)&vl;
}

// m16n8k16 fp16 mma, f32 accumulate
#define MMA_F16(c, a, b) \
    asm("mma.sync.aligned.m16n8k16.row.col.f32.f16.f16.f32 " \
        "{%0,%1,%2,%3}, {%4,%5,%6,%7}, {%8,%9}, {%0,%1,%2,%3};" \
        : "+f"((c)[0]), "+f"((c)[1]), "+f"((c)[2]), "+f"((c)[3]) \
        : "r"((a)[0]), "r"((a)[1]), "r"((a)[2]), "r"((a)[3]), \
          "r"((b)[0]), "r"((b)[1]))

// ========== tensor-core GEMM: C[M,N] = A[M,K] @ W[N,K]^T + bias, opt relu ====
// fp16 2-split (hi+lo, 3 products). CTA tile 128x128, 8 warps (4x2), warp 32x64.
// Smem half [row][k] with row stride 40 halfs -> conflict-free half2 frag loads.
#define KC2  32
#define KSTR 40

__global__ void __launch_bounds__(256, 2)
gemm_h2_kernel(const float* __restrict__ A, const float* __restrict__ W,
               const float* __restrict__ bias, float* __restrict__ C,
               int K, int ldc, int relu)
{
    __shared__ __half As_hi[128*KSTR], As_lo[128*KSTR];
    __shared__ __half Ws_hi[128*KSTR], Ws_lo[128*KSTR];

    const int tid  = threadIdx.x;
    const int wid  = tid >> 5;
    const int lane = tid & 31;
    const int wm   = wid >> 1;          // 0..3
    const int wn   = wid & 1;           // 0..1
    const int gr   = lane >> 2;         // 0..7
    const int gc   = lane & 3;          // 0..3
    const int bx = blockIdx.x, by = blockIdx.y;

    const float* Ab = A + (size_t)(by * 128) * K;
    const float* Wb = W + (size_t)(bx * 128) * K;

    float acc[2][8][4];
#pragma unroll
    for (int mi = 0; mi < 2; mi++)
#pragma unroll
        for (int ni = 0; ni < 8; ni++)
#pragma unroll
            for (int r = 0; r < 4; r++) acc[mi][ni][r] = 0.f;

    // staging: 2 threads per row; thread covers 16 consecutive k (4 float4)
    const int srow = tid >> 1;          // 0..127
    const int skq  = (tid & 1) << 4;    // 0 or 16

    float4 pa[4], pw[4];
#pragma unroll
    for (int j = 0; j < 4; j++) {
        pa[j] = *(const float4*)(Ab + (size_t)srow * K + skq + j * 4);
        pw[j] = *(const float4*)(Wb + (size_t)srow * K + skq + j * 4);
    }

    for (int kt = 0; kt < K; kt += KC2) {
        // ---- split + store current chunk ----
#pragma unroll
        for (int j = 0; j < 4; j++) {
            uint2 h, l;
            split_h2(pa[j].x, pa[j].y, h.x, l.x);
            split_h2(pa[j].z, pa[j].w, h.y, l.y);
            *(uint2*)&As_hi[srow * KSTR + skq + j * 4] = h;
            *(uint2*)&As_lo[srow * KSTR + skq + j * 4] = l;
            split_h2(pw[j].x, pw[j].y, h.x, l.x);
            split_h2(pw[j].z, pw[j].w, h.y, l.y);
            *(uint2*)&Ws_hi[srow * KSTR + skq + j * 4] = h;
            *(uint2*)&Ws_lo[srow * KSTR + skq + j * 4] = l;
        }
        __syncthreads();

        // ---- prefetch next chunk ----
        if (kt + KC2 < K) {
            const int ko = kt + KC2 + skq;
#pragma unroll
            for (int j = 0; j < 4; j++) {
                pa[j] = *(const float4*)(Ab + (size_t)srow * K + ko + j * 4);
                pw[j] = *(const float4*)(Wb + (size_t)srow * K + ko + j * 4);
            }
        }

        // ---- compute: 2 k16 steps ----
#pragma unroll
        for (int kq = 0; kq < KC2; kq += 16) {
            uint32_t ah[2][4], al[2][4];
#pragma unroll
            for (int mi = 0; mi < 2; mi++) {
                const int m0 = wm * 32 + mi * 16;
                const int base = (m0 + gr) * KSTR + kq + gc * 2;
                ah[mi][0] = *(const uint32_t*)&As_hi[base];
                ah[mi][1] = *(const uint32_t*)&As_hi[base + 8 * KSTR];
                ah[mi][2] = *(const uint32_t*)&As_hi[base + 8];
                ah[mi][3] = *(const uint32_t*)&As_hi[base + 8 * KSTR + 8];
                al[mi][0] = *(const uint32_t*)&As_lo[base];
                al[mi][1] = *(const uint32_t*)&As_lo[base + 8 * KSTR];
                al[mi][2] = *(const uint32_t*)&As_lo[base + 8];
                al[mi][3] = *(const uint32_t*)&As_lo[base + 8 * KSTR + 8];
            }
#pragma unroll
            for (int ni = 0; ni < 8; ni++) {
                const int n0 = wn * 64 + ni * 8;
                const int bb = (n0 + gr) * KSTR + kq + gc * 2;
                uint32_t bh[2], bl[2];
                bh[0] = *(const uint32_t*)&Ws_hi[bb];
                bh[1] = *(const uint32_t*)&Ws_hi[bb + 8];
                bl[0] = *(const uint32_t*)&Ws_lo[bb];
                bl[1] = *(const uint32_t*)&Ws_lo[bb + 8];
#pragma unroll
                for (int mi = 0; mi < 2; mi++) {
                    MMA_F16(acc[mi][ni], ah[mi], bh);
                    MMA_F16(acc[mi][ni], ah[mi], bl);
                    MMA_F16(acc[mi][ni], al[mi], bh);
                }
            }
        }
        __syncthreads();
    }

    // ---- epilogue ----
#pragma unroll
    for (int mi = 0; mi < 2; mi++) {
        const int r0 = by * 128 + wm * 32 + mi * 16 + gr;
#pragma unroll
        for (int ni = 0; ni < 8; ni++) {
            const int c = bx * 128 + wn * 64 + ni * 8 + gc * 2;
            const float b0 = bias[c], b1 = bias[c + 1];
            float2 o0, o1;
            o0.x = acc[mi][ni][0] + b0; o0.y = acc[mi][ni][1] + b1;
            o1.x = acc[mi][ni][2] + b0; o1.y = acc[mi][ni][3] + b1;
            if (relu) {
                o0.x = fmaxf(o0.x, 0.f); o0.y = fmaxf(o0.y, 0.f);
                o1.x = fmaxf(o1.x, 0.f); o1.y = fmaxf(o1.y, 0.f);
            }
            *(float2*)(C + (size_t)r0 * ldc + c)       = o0;
            *(float2*)(C + (size_t)(r0 + 8) * ldc + c) = o1;
        }
    }
}

// ---------------- attention scores: S[b,h,q,k] = scale * Q.Kh^T -------------
// K comes from fused KV buffer (row stride KVSTR, K at col offset 0)
__global__ void __launch_bounds__(256)
attn_scores_kernel(const float* __restrict__ Q, const float* __restrict__ KV,
                   float* __restrict__ S)
{
    int z = blockIdx.z;                 // b*H + h
    int b = z >> 4, h = z & 15;
    const float* Qp = Q + (size_t)b * SAQ * EDIM + h * DH;
    const float* Kp = KV + (size_t)b * SBK * KVSTR + h * DH;
    float* Sp = S + (size_t)z * SAQ * SBK;
    int q0 = blockIdx.y * 64, k0 = blockIdx.x * 64;
    int tid = threadIdx.x, tx = tid & 15, ty = tid >> 4;

    __shared__ float Qs[64][64];  // [d][q]
    __shared__ float Ks[64][64];  // [d][k]

#pragma unroll
    for (int i = 0; i < 4; i++) {
        int f = tid + i * 256;          // 0..1023
        int row = f >> 4;               // 0..63
        int dq  = (f & 15) << 2;        // 0..60
        float4 a = *(const float4*)(Qp + (size_t)(q0 + row) * EDIM + dq);
        Qs[dq+0][row] = a.x; Qs[dq+1][row] = a.y;
        Qs[dq+2][row] = a.z; Qs[dq+3][row] = a.w;
        float4 k = *(const float4*)(Kp + (size_t)(k0 + row) * KVSTR + dq);
        Ks[dq+0][row] = k.x; Ks[dq+1][row] = k.y;
        Ks[dq+2][row] = k.z; Ks[dq+3][row] = k.w;
    }
    __syncthreads();

    float acc[4][4];
#pragma unroll
    for (int i = 0; i < 4; i++)
#pragma unroll
        for (int j = 0; j < 4; j++) acc[i][j] = 0.f;

#pragma unroll
    for (int d = 0; d < 64; d++) {
        float4 a = *(const float4*)&Qs[d][ty*4];
        float4 b2 = *(const float4*)&Ks[d][tx*4];
        float av[4] = {a.x,a.y,a.z,a.w};
        float bv[4] = {b2.x,b2.y,b2.z,b2.w};
#pragma unroll
        for (int i = 0; i < 4; i++)
#pragma unroll
            for (int j = 0; j < 4; j++)
                acc[i][j] += av[i] * bv[j];
    }

#pragma unroll
    for (int i = 0; i < 4; i++) {
        float4 v;
        v.x = acc[i][0] * ATT_SCALE; v.y = acc[i][1] * ATT_SCALE;
        v.z = acc[i][2] * ATT_SCALE; v.w = acc[i][3] * ATT_SCALE;
        *(float4*)(Sp + (size_t)(q0 + ty*4 + i) * SBK + k0 + tx*4) = v;
    }
}

// ---------------- row softmax over last dim (512) ---------------------------
__global__ void __launch_bounds__(128)
softmax_kernel(float* __restrict__ S)
{
    size_t row = blockIdx.x;
    float* p = S + row * SBK;
    int tid = threadIdx.x;
    __shared__ float sbuf[4];

    float4 v = ((float4*)p)[tid];
    float m = fmaxf(fmaxf(v.x, v.y), fmaxf(v.z, v.w));
#pragma unroll
    for (int o = 16; o > 0; o >>= 1) m = fmaxf(m, __shfl_xor_sync(0xffffffffu, m, o));
    if ((tid & 31) == 0) sbuf[tid >> 5] = m;
    __syncthreads();
    m = fmaxf(fmaxf(sbuf[0], sbuf[1]), fmaxf(sbuf[2], sbuf[3]));
    __syncthreads();

    float4 e;
    e.x = expf(v.x - m); e.y = expf(v.y - m);
    e.z = expf(v.z - m); e.w = expf(v.w - m);
    float s = e.x + e.y + e.z + e.w;
#pragma unroll
    for (int o = 16; o > 0; o >>= 1) s += __shfl_xor_sync(0xffffffffu, s, o);
    if ((tid & 31) == 0) sbuf[tid >> 5] = s;
    __syncthreads();
    s = sbuf[0] + sbuf[1] + sbuf[2] + sbuf[3];
    float inv = 1.0f / s;
    e.x *= inv; e.y *= inv; e.z *= inv; e.w *= inv;
    ((float4*)p)[tid] = e;
}

// ---------------- ctx[b,q,h*64+d] = sum_k P[z,q,k] * V[b,k,h*64+d] ----------
// V from fused KV buffer at col offset EDIM
__global__ void __launch_bounds__(256)
attn_ctx_kernel(const float* __restrict__ P, const float* __restrict__ KV,
                float* __restrict__ Ctx)
{
    int z = blockIdx.z;
    int b = z >> 4, h = z & 15;
    const float* Pp = P + (size_t)z * SAQ * SBK;
    const float* Vp = KV + (size_t)b * SBK * KVSTR + EDIM + h * DH;
    float* Cp = Ctx + (size_t)b * SAQ * EDIM + h * DH;
    int q0 = blockIdx.y * 64;
    int tid = threadIdx.x, tx = tid & 15, ty = tid >> 4;

    __shared__ float Ps[32][64];  // [k][q]
    __shared__ float Vs[32][64];  // [k][d]

    float acc[4][4];
#pragma unroll
    for (int i = 0; i < 4; i++)
#pragma unroll
        for (int j = 0; j < 4; j++) acc[i][j] = 0.f;

    for (int kt = 0; kt < SBK; kt += 32) {
#pragma unroll
        for (int i = 0; i < 2; i++) {
            int f = tid + i * 256;        // 0..511
            {   // P tile: 64 q rows x 32 k cols
                int row = f >> 3;         // 0..63
                int kq  = (f & 7) << 2;   // 0..28
                float4 p = *(const float4*)(Pp + (size_t)(q0 + row) * SBK + kt + kq);
                Ps[kq+0][row] = p.x; Ps[kq+1][row] = p.y;
                Ps[kq+2][row] = p.z; Ps[kq+3][row] = p.w;
            }
            {   // V tile: 32 k rows x 64 d cols
                int row = f >> 4;         // 0..31
                int dq  = (f & 15) << 2;  // 0..60
                float4 vv = *(const float4*)(Vp + (size_t)(kt + row) * KVSTR + dq);
                *(float4*)&Vs[row][dq] = vv;
            }
        }
        __syncthreads();

#pragma unroll
        for (int kk = 0; kk < 32; kk++) {
            float4 a = *(const float4*)&Ps[kk][ty*4];
            float4 b2 = *(const float4*)&Vs[kk][tx*4];
            float av[4] = {a.x,a.y,a.z,a.w};
            float bv[4] = {b2.x,b2.y,b2.z,b2.w};
#pragma unroll
            for (int i = 0; i < 4; i++)
#pragma unroll
                for (int j = 0; j < 4; j++)
                    acc[i][j] += av[i] * bv[j];
        }
        __syncthreads();
    }

#pragma unroll
    for (int i = 0; i < 4; i++) {
        float4 v;
        v.x = acc[i][0]; v.y = acc[i][1]; v.z = acc[i][2]; v.w = acc[i][3];
        *(float4*)(Cp + (size_t)(q0 + ty*4 + i) * EDIM + tx*4) = v;
    }
}

// ---------------- LayerNorm(residual): Y = LN(X + R) * g + b ----------------
__global__ void __launch_bounds__(256)
ln_residual_kernel(const float* __restrict__ X, const float* __restrict__ R,
                   const float* __restrict__ g, const float* __restrict__ bta,
                   float* __restrict__ Y)
{
    int row = blockIdx.x;
    int tid = threadIdx.x;
    __shared__ float sbuf[8];

    float4 x = ((const float4*)(X + (size_t)row * EDIM))[tid];
    float4 r = ((const float4*)(R + (size_t)row * EDIM))[tid];
    float4 v;
    v.x = x.x + r.x; v.y = x.y + r.y; v.z = x.z + r.z; v.w = x.w + r.w;

    float s = v.x + v.y + v.z + v.w;
#pragma unroll
    for (int o = 16; o > 0; o >>= 1) s += __shfl_xor_sync(0xffffffffu, s, o);
    if ((tid & 31) == 0) sbuf[tid >> 5] = s;
    __syncthreads();
    if (tid < 32) {
        float t = (tid < 8) ? sbuf[tid] : 0.f;
#pragma unroll
        for (int o = 4; o > 0; o >>= 1) t += __shfl_xor_sync(0xffffffffu, t, o);
        if (tid == 0) sbuf[0] = t;
    }
    __syncthreads();
    float mean = sbuf[0] * (1.0f / EDIM);
    __syncthreads();

    float4 d;
    d.x = v.x - mean; d.y = v.y - mean; d.z = v.z - mean; d.w = v.w - mean;
    float sq = d.x*d.x + d.y*d.y + d.z*d.z + d.w*d.w;
#pragma unroll
    for (int o = 16; o > 0; o >>= 1) sq += __shfl_xor_sync(0xffffffffu, sq, o);
    if ((tid & 31) == 0) sbuf[tid >> 5] = sq;
    __syncthreads();
    if (tid < 32) {
        float t = (tid < 8) ? sbuf[tid] : 0.f;
#pragma unroll
        for (int o = 4; o > 0; o >>= 1) t += __shfl_xor_sync(0xffffffffu, t, o);
        if (tid == 0) sbuf[0] = t;
    }
    __syncthreads();
    float var = sbuf[0] * (1.0f / EDIM);
    float inv = rsqrtf(var + EPSV);

    float4 gg = ((const float4*)g)[tid];
    float4 bb = ((const float4*)bta)[tid];
    float4 o4;
    o4.x = d.x * inv * gg.x + bb.x;
    o4.y = d.y * inv * gg.y + bb.y;
    o4.z = d.z * inv * gg.z + bb.z;
    o4.w = d.w * inv * gg.w + bb.w;
    ((float4*)(Y + (size_t)row * EDIM))[tid] = o4;
}

// ---------------- classifier + per-row loss + predicted labels --------------
__global__ void __launch_bounds__(128)
cls_kernel(const float* __restrict__ A, const float* __restrict__ cw,
           const float* __restrict__ cb, const int* __restrict__ mask,
           const int* __restrict__ cand, const int* __restrict__ labels,
           float* __restrict__ out_lab_f, int* __restrict__ out_lab_i,
           int write_float, float* __restrict__ partials)
{
    __shared__ float w0[EDIM];
    __shared__ float w1[EDIM];
    __shared__ float red[128];
    int tid = threadIdx.x;
#pragma unroll
    for (int i = 0; i < EDIM / 128; i++) {
        w0[tid + i * 128] = cw[tid + i * 128];
        w1[tid + i * 128] = cw[EDIM + tid + i * 128];
    }
    __syncthreads();

    int row = blockIdx.x * 128 + tid;
    const float* a = A + (size_t)row * EDIM;
    float e0 = cb[0], e1 = cb[1];
#pragma unroll 4
    for (int i = 0; i < EDIM; i += 4) {
        float4 av = *(const float4*)(a + i);
        e0 += av.x * w0[i] + av.y * w0[i+1] + av.z * w0[i+2] + av.w * w0[i+3];
        e1 += av.x * w1[i] + av.y * w1[i+1] + av.z * w1[i+2] + av.w * w1[i+3];
    }
    int lab = labels[row];
    float m = fmaxf(e0, e1);
    float lse = m + logf(expf(e0 - m) + expf(e1 - m));
    float logp = ((lab == 1) ? e1 : e0) - lse;
    float ce = -logp;
    float w = (lab == 1) ? WEIGHTV : 1.0f;
    float valid = (mask[row] == 1) ? 1.0f : 0.0f;
    float contrib = ce * w * valid;

    int pred = (e1 > e0) ? 1 : 0;
    int pl = (cand[row] == 1 && pred == 1) ? 1 : 0;
    if (write_float) out_lab_f[row] = (float)pl;
    else             out_lab_i[row] = pl;

    red[tid] = contrib;
    __syncthreads();
    for (int o = 64; o > 0; o >>= 1) {
        if (tid < o) red[tid] += red[tid + o];
        __syncthreads();
    }
    if (tid == 0) partials[2 * blockIdx.x] = red[0];
    __syncthreads();
    red[tid] = valid;
    __syncthreads();
    for (int o = 64; o > 0; o >>= 1) {
        if (tid < o) red[tid] += red[tid + o];
        __syncthreads();
    }
    if (tid == 0) partials[2 * blockIdx.x + 1] = red[0];
}

__global__ void finalize_kernel(const float* __restrict__ partials, int nblocks,
                                float* __restrict__ out_loss, int write_float)
{
    if (threadIdx.x == 0 && write_float) {
        float s = 0.f, v = 0.f;
        for (int i = 0; i < nblocks; i++) { s += partials[2*i]; v += partials[2*i+1]; }
        out_loss[0] = s / fmaxf(v, 1.0f);
    }
}

// ---------------------------- host driver -----------------------------------
extern "C" void kernel_launch(void* const* d_in, const int* in_sizes, int n_in,
                              void* d_out, int out_size)
{
    const float* enc   = (const float*)d_in[0];
    const float* desc  = (const float*)d_in[1];
    const int*   maskA = (const int*)  d_in[2];
    const int*   cand  = (const int*)  d_in[3];
    const int*   labels= (const int*)  d_in[4];
    const float* ipw   = (const float*)d_in[5];   // (L, 3E, E)
    const float* ipb   = (const float*)d_in[6];   // (L, 3E)
    const float* outw  = (const float*)d_in[7];   // (L, E, E)
    const float* outb  = (const float*)d_in[8];   // (L, E)
    const float* ln1g  = (const float*)d_in[9];
    const float* ln1b  = (const float*)d_in[10];
    const float* fw1   = (const float*)d_in[11];  // (L, F, E)
    const float* fb1   = (const float*)d_in[12];  // (L, F)
    const float* fw2   = (const float*)d_in[13];  // (L, E, F)
    const float* fb2   = (const float*)d_in[14];  // (L, E)
    const float* ln2g  = (const float*)d_in[15];
    const float* ln2b  = (const float*)d_in[16];
    const float* clsw  = (const float*)d_in[17];  // (C, E)
    const float* clsb  = (const float*)d_in[18];  // (C,)

    float *pA, *pQ, *pKV, *pC, *pO, *pA1, *pS, *pH, *pPart;
    cudaGetSymbolAddress((void**)&pA,  g_bufA);
    cudaGetSymbolAddress((void**)&pQ,  g_bufQ);
    cudaGetSymbolAddress((void**)&pKV, g_bufKV);
    cudaGetSymbolAddress((void**)&pC,  g_bufC);
    cudaGetSymbolAddress((void**)&pO,  g_bufO);
    cudaGetSymbolAddress((void**)&pA1, g_bufA1);
    cudaGetSymbolAddress((void**)&pS,  g_bufS);
    cudaGetSymbolAddress((void**)&pH,  g_bufH);
    cudaGetSymbolAddress((void**)&pPart, g_partials);

    cudaMemsetAsync(d_out, 0, (size_t)out_size * sizeof(float));
    cudaMemcpyAsync(pA, enc, (size_t)NTOK * EDIM * sizeof(float),
                    cudaMemcpyDeviceToDevice);

    const dim3 gemm_tb(256);
    const dim3 g_proj(EDIM / 128, NTOK / 128);         // (8, 32)
    const dim3 g_kv(KVSTR / 128, NTOK / 128);          // (16, 32)
    const dim3 g_ffn1(FFD / 128, NTOK / 128);          // (32, 32)
    const dim3 g_sc(SBK / 64, SAQ / 64, BB * HH);      // (8, 8, 128)
    const dim3 g_ctx(1, SAQ / 64, BB * HH);            // (1, 8, 128)

    for (int l = 0; l < LL; l++) {
        const float* wq = ipw + (size_t)l * 3 * EDIM * EDIM;
        const float* wkv = wq + (size_t)EDIM * EDIM;       // wk|wv contiguous
        const float* bq = ipb + (size_t)l * 3 * EDIM;
        const float* bkv = bq + EDIM;                      // bk|bv contiguous

        gemm_h2_kernel<<<g_proj, gemm_tb>>>(pA,   wq,  bq,  pQ,  EDIM, EDIM, 0);
        gemm_h2_kernel<<<g_kv,   gemm_tb>>>(desc, wkv, bkv, pKV, EDIM, KVSTR, 0);

        attn_scores_kernel<<<g_sc, 256>>>(pQ, pKV, pS);
        softmax_kernel<<<BB * HH * SAQ, 128>>>(pS);
        attn_ctx_kernel<<<g_ctx, 256>>>(pS, pKV, pC);

        gemm_h2_kernel<<<g_proj, gemm_tb>>>(pC, outw + (size_t)l * EDIM * EDIM,
                                            outb + (size_t)l * EDIM, pO,
                                            EDIM, EDIM, 0);

        ln_residual_kernel<<<NTOK, 256>>>(pA, pO, ln1g + (size_t)l * EDIM,
                                          ln1b + (size_t)l * EDIM, pA1);

        gemm_h2_kernel<<<g_ffn1, gemm_tb>>>(pA1, fw1 + (size_t)l * FFD * EDIM,
                                            fb1 + (size_t)l * FFD, pH,
                                            EDIM, FFD, 1);
        gemm_h2_kernel<<<g_proj, gemm_tb>>>(pH, fw2 + (size_t)l * EDIM * FFD,
                                            fb2 + (size_t)l * EDIM, pO,
                                            FFD, EDIM, 0);

        ln_residual_kernel<<<NTOK, 256>>>(pA1, pO, ln2g + (size_t)l * EDIM,
                                          ln2b + (size_t)l * EDIM, pA);
    }

    int write_float = (out_size > NTOK) ? 1 : 0;
    int lab_off = write_float ? (out_size - NTOK) : 0;
    float* outf = (float*)d_out;
    int*   outi = (int*)d_out;

    cls_kernel<<<NTOK / 128, 128>>>(pA, clsw, clsb, maskA, cand, labels,
                                    outf + lab_off, outi, write_float, pPart);
    finalize_kernel<<<1, 32>>>(pPart, NTOK / 128, outf, write_float);
}

// round 8
// speedup vs baseline: 1.9846x; 1.1425x over previous
#include <cuda_runtime.h>
#include <cuda_fp16.h>
#include <math.h>
#include <stdint.h>

// Problem constants
#define BB    8
#define SAQ   512
#define SBK   512
#define EDIM  1024
#define HH    16
#define DH    64
#define FFD   4096
#define LL    9
#define NTOK  (BB*SAQ)          // 4096 rows
#define WEIGHTV 5.0f
#define EPSV    1e-5f
#define ATT_SCALE 0.125f        // 1/sqrt(64)
#define KVSTR 2048              // fused K|V row stride

// ---------------- scratch (device globals; no allocation allowed) ------------
__device__ float g_bufA [NTOK*EDIM];
__device__ float g_bufQ [NTOK*EDIM];
__device__ float g_bufKV[NTOK*KVSTR];              // [row][0:1024]=K, [1024:2048]=V
__device__ float g_bufC [NTOK*EDIM];
__device__ float g_bufO [NTOK*EDIM];
__device__ float g_bufA1[NTOK*EDIM];
__device__ float g_bufS [(size_t)BB*HH*SAQ*SBK];   // 33.5M floats
__device__ float g_bufH [(size_t)NTOK*FFD];        // 16.7M floats
__device__ float g_partials[64];

// ---------------- fp16 split helpers -----------------------------------------
__device__ __forceinline__ void split_h2(float x, float y,
                                         uint32_t& hi, uint32_t& lo) {
    __half hx = __float2half_rn(x), hy = __float2half_rn(y);
    __half lx = __float2half_rn(x - __half2float(hx));
    __half ly = __float2half_rn(y - __half2float(hy));
    __half2 vh = __halves2half2(hx, hy);
    __half2 vl = __halves2half2(lx, ly);
    hi = *(uint32_t*)&vh;
    lo = *(uint32_t*)&vl;
}

// m16n8k16 fp16 mma, f32 accumulate
#define MMA_F16(c, a, b) \
    asm("mma.sync.aligned.m16n8k16.row.col.f32.f16.f16.f32 " \
        "{%0,%1,%2,%3}, {%4,%5,%6,%7}, {%8,%9}, {%0,%1,%2,%3};" \
        : "+f"((c)[0]), "+f"((c)[1]), "+f"((c)[2]), "+f"((c)[3]) \
        : "r"((a)[0]), "r"((a)[1]), "r"((a)[2]), "r"((a)[3]), \
          "r"((b)[0]), "r"((b)[1]))

#define KC2  32
#define KSTR 40

// ========== core: 128x128 output tile, fp16 2-split (3 products) =============
// C[m,n] = alpha * sum_k A[m,k]*W[n,k] + bias[n]; A rows lda, W rows ldw.
__device__ __forceinline__ void gemm128_core(
    const float* __restrict__ Ab, int lda,
    const float* __restrict__ Wb, int ldw,
    const float* __restrict__ biasb,      // nullable, col-local
    float* __restrict__ Cb, int ldc,
    int K, float alpha, int relu)
{
    __shared__ __half As_hi[128*KSTR], As_lo[128*KSTR];
    __shared__ __half Ws_hi[128*KSTR], Ws_lo[128*KSTR];

    const int tid  = threadIdx.x;
    const int wid  = tid >> 5;
    const int lane = tid & 31;
    const int wm   = wid >> 1;          // 0..3
    const int wn   = wid & 1;           // 0..1
    const int gr   = lane >> 2;         // 0..7
    const int gc   = lane & 3;          // 0..3

    float acc[2][8][4];
#pragma unroll
    for (int mi = 0; mi < 2; mi++)
#pragma unroll
        for (int ni = 0; ni < 8; ni++)
#pragma unroll
            for (int r = 0; r < 4; r++) acc[mi][ni][r] = 0.f;

    const int srow = tid >> 1;          // 0..127
    const int skq  = (tid & 1) << 4;    // 0 or 16

    float4 pa[4], pw[4];
#pragma unroll
    for (int j = 0; j < 4; j++) {
        pa[j] = *(const float4*)(Ab + (size_t)srow * lda + skq + j * 4);
        pw[j] = *(const float4*)(Wb + (size_t)srow * ldw + skq + j * 4);
    }

    for (int kt = 0; kt < K; kt += KC2) {
#pragma unroll
        for (int j = 0; j < 4; j++) {
            uint2 h, l;
            split_h2(pa[j].x, pa[j].y, h.x, l.x);
            split_h2(pa[j].z, pa[j].w, h.y, l.y);
            *(uint2*)&As_hi[srow * KSTR + skq + j * 4] = h;
            *(uint2*)&As_lo[srow * KSTR + skq + j * 4] = l;
            split_h2(pw[j].x, pw[j].y, h.x, l.x);
            split_h2(pw[j].z, pw[j].w, h.y, l.y);
            *(uint2*)&Ws_hi[srow * KSTR + skq + j * 4] = h;
            *(uint2*)&Ws_lo[srow * KSTR + skq + j * 4] = l;
        }
        __syncthreads();

        if (kt + KC2 < K) {
            const int ko = kt + KC2 + skq;
#pragma unroll
            for (int j = 0; j < 4; j++) {
                pa[j] = *(const float4*)(Ab + (size_t)srow * lda + ko + j * 4);
                pw[j] = *(const float4*)(Wb + (size_t)srow * ldw + ko + j * 4);
            }
        }

#pragma unroll
        for (int kq = 0; kq < KC2; kq += 16) {
            uint32_t ah[2][4], al[2][4];
#pragma unroll
            for (int mi = 0; mi < 2; mi++) {
                const int m0 = wm * 32 + mi * 16;
                const int base = (m0 + gr) * KSTR + kq + gc * 2;
                ah[mi][0] = *(const uint32_t*)&As_hi[base];
                ah[mi][1] = *(const uint32_t*)&As_hi[base + 8 * KSTR];
                ah[mi][2] = *(const uint32_t*)&As_hi[base + 8];
                ah[mi][3] = *(const uint32_t*)&As_hi[base + 8 * KSTR + 8];
                al[mi][0] = *(const uint32_t*)&As_lo[base];
                al[mi][1] = *(const uint32_t*)&As_lo[base + 8 * KSTR];
                al[mi][2] = *(const uint32_t*)&As_lo[base + 8];
                al[mi][3] = *(const uint32_t*)&As_lo[base + 8 * KSTR + 8];
            }
#pragma unroll
            for (int ni = 0; ni < 8; ni++) {
                const int n0 = wn * 64 + ni * 8;
                const int bb = (n0 + gr) * KSTR + kq + gc * 2;
                uint32_t bh[2], bl[2];
                bh[0] = *(const uint32_t*)&Ws_hi[bb];
                bh[1] = *(const uint32_t*)&Ws_hi[bb + 8];
                bl[0] = *(const uint32_t*)&Ws_lo[bb];
                bl[1] = *(const uint32_t*)&Ws_lo[bb + 8];
#pragma unroll
                for (int mi = 0; mi < 2; mi++) {
                    MMA_F16(acc[mi][ni], ah[mi], bh);
                    MMA_F16(acc[mi][ni], ah[mi], bl);
                    MMA_F16(acc[mi][ni], al[mi], bh);
                }
            }
        }
        __syncthreads();
    }

#pragma unroll
    for (int mi = 0; mi < 2; mi++) {
        const int r0 = wm * 32 + mi * 16 + gr;
#pragma unroll
        for (int ni = 0; ni < 8; ni++) {
            const int c = wn * 64 + ni * 8 + gc * 2;
            float b0 = 0.f, b1 = 0.f;
            if (biasb) { b0 = biasb[c]; b1 = biasb[c + 1]; }
            float2 o0, o1;
            o0.x = acc[mi][ni][0] * alpha + b0; o0.y = acc[mi][ni][1] * alpha + b1;
            o1.x = acc[mi][ni][2] * alpha + b0; o1.y = acc[mi][ni][3] * alpha + b1;
            if (relu) {
                o0.x = fmaxf(o0.x, 0.f); o0.y = fmaxf(o0.y, 0.f);
                o1.x = fmaxf(o1.x, 0.f); o1.y = fmaxf(o1.y, 0.f);
            }
            *(float2*)(Cb + (size_t)r0 * ldc + c)       = o0;
            *(float2*)(Cb + (size_t)(r0 + 8) * ldc + c) = o1;
        }
    }
}

// ---- weights GEMM: C[M,N] = A[M,K] @ W[N,K]^T + bias ----
__global__ void __launch_bounds__(256, 2)
gemm_h2_kernel(const float* __restrict__ A, const float* __restrict__ W,
               const float* __restrict__ bias, float* __restrict__ C,
               int K, int ldc, int relu)
{
    gemm128_core(A + (size_t)(blockIdx.y * 128) * K, K,
                 W + (size_t)(blockIdx.x * 128) * K, K,
                 bias + blockIdx.x * 128,
                 C + (size_t)(blockIdx.y * 128) * ldc + blockIdx.x * 128, ldc,
                 K, 1.f, relu);
}

// ---- attention scores via mma: S[z,q,k] = scale * Q_h . K_h^T ----
__global__ void __launch_bounds__(256, 2)
attn_scores_mma_kernel(const float* __restrict__ Q, const float* __restrict__ KV,
                       float* __restrict__ S)
{
    const int z = blockIdx.z, b = z >> 4, h = z & 15;
    const float* Ab = Q + (size_t)b * SAQ * EDIM
                        + (size_t)(blockIdx.y * 128) * EDIM + h * DH;
    const float* Wb = KV + (size_t)b * SBK * KVSTR
                         + (size_t)(blockIdx.x * 128) * KVSTR + h * DH;
    float* Cb = S + (size_t)z * SAQ * SBK
                  + (size_t)(blockIdx.y * 128) * SBK + blockIdx.x * 128;
    gemm128_core(Ab, EDIM, Wb, KVSTR, nullptr, Cb, SBK, DH, ATT_SCALE, 0);
}

// ---- attention ctx via mma: Ctx[b,q,h*64+d] = sum_k P[z,q,k] * V[b,k,h*64+d]
// CTA tile 128(M=q) x 64(N=d), warps 4x2 (warp 32x32). V transposed in staging.
__global__ void __launch_bounds__(256, 2)
attn_ctx_mma_kernel(const float* __restrict__ P, const float* __restrict__ KV,
                    float* __restrict__ Ctx)
{
    __shared__ __half As_hi[128*KSTR], As_lo[128*KSTR];
    __shared__ __half Ws_hi[64*KSTR],  Ws_lo[64*KSTR];

    const int z = blockIdx.z, b = z >> 4, h = z & 15;
    const int q0 = blockIdx.y * 128;
    const float* Pp = P + (size_t)z * SAQ * SBK + (size_t)q0 * SBK;
    const float* Vp = KV + (size_t)b * SBK * KVSTR + EDIM + h * DH;

    const int tid  = threadIdx.x;
    const int wid  = tid >> 5;
    const int lane = tid & 31;
    const int wm   = wid >> 1;          // 0..3 (q, 32 rows)
    const int wn   = wid & 1;           // 0..1 (d, 32 cols)
    const int gr   = lane >> 2;
    const int gc   = lane & 3;

    float acc[2][4][4];
#pragma unroll
    for (int mi = 0; mi < 2; mi++)
#pragma unroll
        for (int ni = 0; ni < 4; ni++)
#pragma unroll
            for (int r = 0; r < 4; r++) acc[mi][ni][r] = 0.f;

    const int srow = tid >> 1;          // 0..127 (q rows)
    const int skq  = (tid & 1) << 4;    // 0/16

    float4 pa[4], pv[2];
#pragma unroll
    for (int j = 0; j < 4; j++)
        pa[j] = *(const float4*)(Pp + (size_t)srow * SBK + skq + j * 4);
#pragma unroll
    for (int i = 0; i < 2; i++) {
        int f = tid + i * 256;              // 0..511
        int krow = f >> 4, dq = (f & 15) << 2;
        pv[i] = *(const float4*)(Vp + (size_t)krow * KVSTR + dq);
    }

    for (int kt = 0; kt < SBK; kt += KC2) {
        // stage P tile [128 q][32 k]
#pragma unroll
        for (int j = 0; j < 4; j++) {
            uint2 hh, ll;
            split_h2(pa[j].x, pa[j].y, hh.x, ll.x);
            split_h2(pa[j].z, pa[j].w, hh.y, ll.y);
            *(uint2*)&As_hi[srow * KSTR + skq + j * 4] = hh;
            *(uint2*)&As_lo[srow * KSTR + skq + j * 4] = ll;
        }
        // stage V^T tile: Ws[d][k] <- V[kt+k][d], 32 k x 64 d
#pragma unroll
        for (int i = 0; i < 2; i++) {
            int f = tid + i * 256;
            int krow = f >> 4, dq = (f & 15) << 2;
            const float v4[4] = {pv[i].x, pv[i].y, pv[i].z, pv[i].w};
#pragma unroll
            for (int j = 0; j < 4; j++) {
                __half vh = __float2half_rn(v4[j]);
                __half vl = __float2half_rn(v4[j] - __half2float(vh));
                Ws_hi[(dq + j) * KSTR + krow] = vh;
                Ws_lo[(dq + j) * KSTR + krow] = vl;
            }
        }
        __syncthreads();

        if (kt + KC2 < SBK) {
            const int ko = kt + KC2;
#pragma unroll
            for (int j = 0; j < 4; j++)
                pa[j] = *(const float4*)(Pp + (size_t)srow * SBK + ko + skq + j * 4);
#pragma unroll
            for (int i = 0; i < 2; i++) {
                int f = tid + i * 256;
                int krow = f >> 4, dq = (f & 15) << 2;
                pv[i] = *(const float4*)(Vp + (size_t)(ko + krow) * KVSTR + dq);
            }
        }

#pragma unroll
        for (int kq = 0; kq < KC2; kq += 16) {
            uint32_t ah[2][4], al[2][4];
#pragma unroll
            for (int mi = 0; mi < 2; mi++) {
                const int m0 = wm * 32 + mi * 16;
                const int base = (m0 + gr) * KSTR + kq + gc * 2;
                ah[mi][0] = *(const uint32_t*)&As_hi[base];
                ah[mi][1] = *(const uint32_t*)&As_hi[base + 8 * KSTR];
                ah[mi][2] = *(const uint32_t*)&As_hi[base + 8];
                ah[mi][3] = *(const uint32_t*)&As_hi[base + 8 * KSTR + 8];
                al[mi][0] = *(const uint32_t*)&As_lo[base];
                al[mi][1] = *(const uint32_t*)&As_lo[base + 8 * KSTR];
                al[mi][2] = *(const uint32_t*)&As_lo[base + 8];
                al[mi][3] = *(const uint32_t*)&As_lo[base + 8 * KSTR + 8];
            }
#pragma unroll
            for (int ni = 0; ni < 4; ni++) {
                const int n0 = wn * 32 + ni * 8;
                const int bb = (n0 + gr) * KSTR + kq + gc * 2;
                uint32_t bh[2], bl[2];
                bh[0] = *(const uint32_t*)&Ws_hi[bb];
                bh[1] = *(const uint32_t*)&Ws_hi[bb + 8];
                bl[0] = *(const uint32_t*)&Ws_lo[bb];
                bl[1] = *(const uint32_t*)&Ws_lo[bb + 8];
#pragma unroll
                for (int mi = 0; mi < 2; mi++) {
                    MMA_F16(acc[mi][ni], ah[mi], bh);
                    MMA_F16(acc[mi][ni], ah[mi], bl);
                    MMA_F16(acc[mi][ni], al[mi], bh);
                }
            }
        }
        __syncthreads();
    }

    float* Cp = Ctx + (size_t)(b * SAQ + q0) * EDIM + h * DH;
#pragma unroll
    for (int mi = 0; mi < 2; mi++) {
        const int r0 = wm * 32 + mi * 16 + gr;
#pragma unroll
        for (int ni = 0; ni < 4; ni++) {
            const int c = wn * 32 + ni * 8 + gc * 2;
            float2 o0, o1;
            o0.x = acc[mi][ni][0]; o0.y = acc[mi][ni][1];
            o1.x = acc[mi][ni][2]; o1.y = acc[mi][ni][3];
            *(float2*)(Cp + (size_t)r0 * EDIM + c)       = o0;
            *(float2*)(Cp + (size_t)(r0 + 8) * EDIM + c) = o1;
        }
    }
}

// ---------------- row softmax over last dim (512) ---------------------------
__global__ void __launch_bounds__(128)
softmax_kernel(float* __restrict__ S)
{
    size_t row = blockIdx.x;
    float* p = S + row * SBK;
    int tid = threadIdx.x;
    __shared__ float sbuf[4];

    float4 v = ((float4*)p)[tid];
    float m = fmaxf(fmaxf(v.x, v.y), fmaxf(v.z, v.w));
#pragma unroll
    for (int o = 16; o > 0; o >>= 1) m = fmaxf(m, __shfl_xor_sync(0xffffffffu, m, o));
    if ((tid & 31) == 0) sbuf[tid >> 5] = m;
    __syncthreads();
    m = fmaxf(fmaxf(sbuf[0], sbuf[1]), fmaxf(sbuf[2], sbuf[3]));
    __syncthreads();

    float4 e;
    e.x = expf(v.x - m); e.y = expf(v.y - m);
    e.z = expf(v.z - m); e.w = expf(v.w - m);
    float s = e.x + e.y + e.z + e.w;
#pragma unroll
    for (int o = 16; o > 0; o >>= 1) s += __shfl_xor_sync(0xffffffffu, s, o);
    if ((tid & 31) == 0) sbuf[tid >> 5] = s;
    __syncthreads();
    s = sbuf[0] + sbuf[1] + sbuf[2] + sbuf[3];
    float inv = 1.0f / s;
    e.x *= inv; e.y *= inv; e.z *= inv; e.w *= inv;
    ((float4*)p)[tid] = e;
}

// ---------------- LayerNorm(residual): Y = LN(X + R) * g + b ----------------
__global__ void __launch_bounds__(256)
ln_residual_kernel(const float* __restrict__ X, const float* __restrict__ R,
                   const float* __restrict__ g, const float* __restrict__ bta,
                   float* __restrict__ Y)
{
    int row = blockIdx.x;
    int tid = threadIdx.x;
    __shared__ float sbuf[8];

    float4 x = ((const float4*)(X + (size_t)row * EDIM))[tid];
    float4 r = ((const float4*)(R + (size_t)row * EDIM))[tid];
    float4 v;
    v.x = x.x + r.x; v.y = x.y + r.y; v.z = x.z + r.z; v.w = x.w + r.w;

    float s = v.x + v.y + v.z + v.w;
#pragma unroll
    for (int o = 16; o > 0; o >>= 1) s += __shfl_xor_sync(0xffffffffu, s, o);
    if ((tid & 31) == 0) sbuf[tid >> 5] = s;
    __syncthreads();
    if (tid < 32) {
        float t = (tid < 8) ? sbuf[tid] : 0.f;
#pragma unroll
        for (int o = 4; o > 0; o >>= 1) t += __shfl_xor_sync(0xffffffffu, t, o);
        if (tid == 0) sbuf[0] = t;
    }
    __syncthreads();
    float mean = sbuf[0] * (1.0f / EDIM);
    __syncthreads();

    float4 d;
    d.x = v.x - mean; d.y = v.y - mean; d.z = v.z - mean; d.w = v.w - mean;
    float sq = d.x*d.x + d.y*d.y + d.z*d.z + d.w*d.w;
#pragma unroll
    for (int o = 16; o > 0; o >>= 1) sq += __shfl_xor_sync(0xffffffffu, sq, o);
    if ((tid & 31) == 0) sbuf[tid >> 5] = sq;
    __syncthreads();
    if (tid < 32) {
        float t = (tid < 8) ? sbuf[tid] : 0.f;
#pragma unroll
        for (int o = 4; o > 0; o >>= 1) t += __shfl_xor_sync(0xffffffffu, t, o);
        if (tid == 0) sbuf[0] = t;
    }
    __syncthreads();
    float var = sbuf[0] * (1.0f / EDIM);
    float inv = rsqrtf(var + EPSV);

    float4 gg = ((const float4*)g)[tid];
    float4 bb = ((const float4*)bta)[tid];
    float4 o4;
    o4.x = d.x * inv * gg.x + bb.x;
    o4.y = d.y * inv * gg.y + bb.y;
    o4.z = d.z * inv * gg.z + bb.z;
    o4.w = d.w * inv * gg.w + bb.w;
    ((float4*)(Y + (size_t)row * EDIM))[tid] = o4;
}

// ---------------- classifier + per-row loss + predicted labels --------------
__global__ void __launch_bounds__(128)
cls_kernel(const float* __restrict__ A, const float* __restrict__ cw,
           const float* __restrict__ cb, const int* __restrict__ mask,
           const int* __restrict__ cand, const int* __restrict__ labels,
           float* __restrict__ out_lab_f, int* __restrict__ out_lab_i,
           int write_float, float* __restrict__ partials)
{
    __shared__ float w0[EDIM];
    __shared__ float w1[EDIM];
    __shared__ float red[128];
    int tid = threadIdx.x;
#pragma unroll
    for (int i = 0; i < EDIM / 128; i++) {
        w0[tid + i * 128] = cw[tid + i * 128];
        w1[tid + i * 128] = cw[EDIM + tid + i * 128];
    }
    __syncthreads();

    int row = blockIdx.x * 128 + tid;
    const float* a = A + (size_t)row * EDIM;
    float e0 = cb[0], e1 = cb[1];
#pragma unroll 4
    for (int i = 0; i < EDIM; i += 4) {
        float4 av = *(const float4*)(a + i);
        e0 += av.x * w0[i] + av.y * w0[i+1] + av.z * w0[i+2] + av.w * w0[i+3];
        e1 += av.x * w1[i] + av.y * w1[i+1] + av.z * w1[i+2] + av.w * w1[i+3];
    }
    int lab = labels[row];
    float m = fmaxf(e0, e1);
    float lse = m + logf(expf(e0 - m) + expf(e1 - m));
    float logp = ((lab == 1) ? e1 : e0) - lse;
    float ce = -logp;
    float w = (lab == 1) ? WEIGHTV : 1.0f;
    float valid = (mask[row] == 1) ? 1.0f : 0.0f;
    float contrib = ce * w * valid;

    int pred = (e1 > e0) ? 1 : 0;
    int pl = (cand[row] == 1 && pred == 1) ? 1 : 0;
    if (write_float) out_lab_f[row] = (float)pl;
    else             out_lab_i[row] = pl;

    red[tid] = contrib;
    __syncthreads();
    for (int o = 64; o > 0; o >>= 1) {
        if (tid < o) red[tid] += red[tid + o];
        __syncthreads();
    }
    if (tid == 0) partials[2 * blockIdx.x] = red[0];
    __syncthreads();
    red[tid] = valid;
    __syncthreads();
    for (int o = 64; o > 0; o >>= 1) {
        if (tid < o) red[tid] += red[tid + o];
        __syncthreads();
    }
    if (tid == 0) partials[2 * blockIdx.x + 1] = red[0];
}

__global__ void finalize_kernel(const float* __restrict__ partials, int nblocks,
                                float* __restrict__ out_loss, int write_float)
{
    if (threadIdx.x == 0 && write_float) {
        float s = 0.f, v = 0.f;
        for (int i = 0; i < nblocks; i++) { s += partials[2*i]; v += partials[2*i+1]; }
        out_loss[0] = s / fmaxf(v, 1.0f);
    }
}

// ---------------------------- host driver -----------------------------------
extern "C" void kernel_launch(void* const* d_in, const int* in_sizes, int n_in,
                              void* d_out, int out_size)
{
    const float* enc   = (const float*)d_in[0];
    const float* desc  = (const float*)d_in[1];
    const int*   maskA = (const int*)  d_in[2];
    const int*   cand  = (const int*)  d_in[3];
    const int*   labels= (const int*)  d_in[4];
    const float* ipw   = (const float*)d_in[5];   // (L, 3E, E)
    const float* ipb   = (const float*)d_in[6];   // (L, 3E)
    const float* outw  = (const float*)d_in[7];   // (L, E, E)
    const float* outb  = (const float*)d_in[8];   // (L, E)
    const float* ln1g  = (const float*)d_in[9];
    const float* ln1b  = (const float*)d_in[10];
    const float* fw1   = (const float*)d_in[11];  // (L, F, E)
    const float* fb1   = (const float*)d_in[12];  // (L, F)
    const float* fw2   = (const float*)d_in[13];  // (L, E, F)
    const float* fb2   = (const float*)d_in[14];  // (L, E)
    const float* ln2g  = (const float*)d_in[15];
    const float* ln2b  = (const float*)d_in[16];
    const float* clsw  = (const float*)d_in[17];  // (C, E)
    const float* clsb  = (const float*)d_in[18];  // (C,)

    float *pA, *pQ, *pKV, *pC, *pO, *pA1, *pS, *pH, *pPart;
    cudaGetSymbolAddress((void**)&pA,  g_bufA);
    cudaGetSymbolAddress((void**)&pQ,  g_bufQ);
    cudaGetSymbolAddress((void**)&pKV, g_bufKV);
    cudaGetSymbolAddress((void**)&pC,  g_bufC);
    cudaGetSymbolAddress((void**)&pO,  g_bufO);
    cudaGetSymbolAddress((void**)&pA1, g_bufA1);
    cudaGetSymbolAddress((void**)&pS,  g_bufS);
    cudaGetSymbolAddress((void**)&pH,  g_bufH);
    cudaGetSymbolAddress((void**)&pPart, g_partials);

    cudaMemsetAsync(d_out, 0, (size_t)out_size * sizeof(float));
    cudaMemcpyAsync(pA, enc, (size_t)NTOK * EDIM * sizeof(float),
                    cudaMemcpyDeviceToDevice);

    const dim3 gemm_tb(256);
    const dim3 g_proj(EDIM / 128, NTOK / 128);         // (8, 32)
    const dim3 g_kv(KVSTR / 128, NTOK / 128);          // (16, 32)
    const dim3 g_ffn1(FFD / 128, NTOK / 128);          // (32, 32)
    const dim3 g_sc(SBK / 128, SAQ / 128, BB * HH);    // (4, 4, 128)
    const dim3 g_ctx(1, SAQ / 128, BB * HH);           // (1, 4, 128)

    for (int l = 0; l < LL; l++) {
        const float* wq = ipw + (size_t)l * 3 * EDIM * EDIM;
        const float* wkv = wq + (size_t)EDIM * EDIM;       // wk|wv contiguous
        const float* bq = ipb + (size_t)l * 3 * EDIM;
        const float* bkv = bq + EDIM;                      // bk|bv contiguous

        gemm_h2_kernel<<<g_proj, gemm_tb>>>(pA,   wq,  bq,  pQ,  EDIM, EDIM, 0);
        gemm_h2_kernel<<<g_kv,   gemm_tb>>>(desc, wkv, bkv, pKV, EDIM, KVSTR, 0);

        attn_scores_mma_kernel<<<g_sc, gemm_tb>>>(pQ, pKV, pS);
        softmax_kernel<<<BB * HH * SAQ, 128>>>(pS);
        attn_ctx_mma_kernel<<<g_ctx, gemm_tb>>>(pS, pKV, pC);

        gemm_h2_kernel<<<g_proj, gemm_tb>>>(pC, outw + (size_t)l * EDIM * EDIM,
                                            outb + (size_t)l * EDIM, pO,
                                            EDIM, EDIM, 0);

        ln_residual_kernel<<<NTOK, 256>>>(pA, pO, ln1g + (size_t)l * EDIM,
                                          ln1b + (size_t)l * EDIM, pA1);

        gemm_h2_kernel<<<g_ffn1, gemm_tb>>>(pA1, fw1 + (size_t)l * FFD * EDIM,
                                            fb1 + (size_t)l * FFD, pH,
                                            EDIM, FFD, 1);
        gemm_h2_kernel<<<g_proj, gemm_tb>>>(pH, fw2 + (size_t)l * EDIM * FFD,
                                            fb2 + (size_t)l * EDIM, pO,
                                            FFD, EDIM, 0);

        ln_residual_kernel<<<NTOK, 256>>>(pA1, pO, ln2g + (size_t)l * EDIM,
                                          ln2b + (size_t)l * EDIM, pA);
    }

    int write_float = (out_size > NTOK) ? 1 : 0;
    int lab_off = write_float ? (out_size - NTOK) : 0;
    float* outf = (float*)d_out;
    int*   outi = (int*)d_out;

    cls_kernel<<<NTOK / 128, 128>>>(pA, clsw, clsb, maskA, cand, labels,
                                    outf + lab_off, outi, write_float, pPart);
    finalize_kernel<<<1, 32>>>(pPart, NTOK / 128, outf, write_float);
}

// round 9
// speedup vs baseline: 2.1819x; 1.0994x over previous
#include <cuda_runtime.h>
#include <cuda_fp16.h>
#include <math.h>
#include <stdint.h>

// Problem constants
#define BB    8
#define SAQ   512
#define SBK   512
#define EDIM  1024
#define HH    16
#define DH    64
#define FFD   4096
#define LL    9
#define NTOK  (BB*SAQ)
#define WEIGHTV 5.0f
#define EPSV    1e-5f
#define ATT_SCALE 0.125f
#define KVSTR 2048

#define KC    32
#define KSTR  40
#define ST128_HALFS (4*128*KSTR)       // 20480
#define ST128_BYTES (ST128_HALFS*2)    // 40960
#define ST64_HALFS  (384*KSTR)         // 15360
#define ST64_BYTES  (ST64_HALFS*2)     // 30720

// ---------------- scratch (device globals) -----------------------------------
__device__ float g_Af [NTOK*EDIM];
__device__ float g_A1f[NTOK*EDIM];
__device__ float g_Of [NTOK*EDIM];
__device__ float g_Sf [(size_t)BB*HH*SAQ*SBK];
__device__ float g_partials[64];

__device__ __half g_wip_h[(size_t)LL*3*EDIM*EDIM], g_wip_l[(size_t)LL*3*EDIM*EDIM];
__device__ __half g_wout_h[(size_t)LL*EDIM*EDIM],  g_wout_l[(size_t)LL*EDIM*EDIM];
__device__ __half g_wf1_h[(size_t)LL*FFD*EDIM],    g_wf1_l[(size_t)LL*FFD*EDIM];
__device__ __half g_wf2_h[(size_t)LL*EDIM*FFD],    g_wf2_l[(size_t)LL*EDIM*FFD];

__device__ __half g_sA_h [NTOK*EDIM],  g_sA_l [NTOK*EDIM];
__device__ __half g_sA1_h[NTOK*EDIM],  g_sA1_l[NTOK*EDIM];
__device__ __half g_sD_h [NTOK*EDIM],  g_sD_l [NTOK*EDIM];
__device__ __half g_sQ_h [NTOK*EDIM],  g_sQ_l [NTOK*EDIM];
__device__ __half g_sKV_h[(size_t)NTOK*KVSTR], g_sKV_l[(size_t)NTOK*KVSTR];
__device__ __half g_sC_h [NTOK*EDIM],  g_sC_l [NTOK*EDIM];
__device__ __half g_sH_h [(size_t)NTOK*FFD],   g_sH_l [(size_t)NTOK*FFD];
__device__ __half g_sP_h [(size_t)BB*HH*SAQ*SBK], g_sP_l[(size_t)BB*HH*SAQ*SBK];
__device__ __half g_sVT_h[(size_t)BB*EDIM*SBK],   g_sVT_l[(size_t)BB*EDIM*SBK];

// ---------------- helpers ----------------------------------------------------
__device__ __forceinline__ uint32_t smem_u32(const void* p){
    uint32_t a;
    asm("{ .reg .u64 t; cvta.to.shared.u64 t, %1; cvt.u32.u64 %0, t; }"
        : "=r"(a) : "l"(p));
    return a;
}
#define CP16(dst,src) asm volatile("cp.async.cg.shared.global [%0], [%1], 16;"::"r"(dst),"l"(src))
#define CPC()  asm volatile("cp.async.commit_group;":::"memory")
#define CPW1() asm volatile("cp.async.wait_group 1;":::"memory")
#define CPW0() asm volatile("cp.async.wait_group 0;":::"memory")

#define MMA_F16(c, a, b) \
    asm("mma.sync.aligned.m16n8k16.row.col.f32.f16.f16.f32 " \
        "{%0,%1,%2,%3}, {%4,%5,%6,%7}, {%8,%9}, {%0,%1,%2,%3};" \
        : "+f"((c)[0]), "+f"((c)[1]), "+f"((c)[2]), "+f"((c)[3]) \
        : "r"((a)[0]), "r"((a)[1]), "r"((a)[2]), "r"((a)[3]), \
          "r"((b)[0]), "r"((b)[1]))

// ========== core: 128x128 tile, pre-split fp16 inputs, cp.async pipeline =====
__device__ __forceinline__ void gemm128_core(
    const __half* __restrict__ Ahi, const __half* __restrict__ Alo, int lda,
    const __half* __restrict__ Whi, const __half* __restrict__ Wlo, int ldw,
    const float* __restrict__ bias,
    float* __restrict__ Cf, __half* __restrict__ Chi, __half* __restrict__ Clo,
    int ldc, int K, float alpha, int relu)
{
    extern __shared__ __half sm[];
    const uint32_t smb = smem_u32(sm);
    const int tid = threadIdx.x;
    const int wid = tid >> 5, lane = tid & 31;
    const int wm = wid >> 1, wn = wid & 1, gr = lane >> 2, gc = lane & 3;

    float acc[2][8][4];
#pragma unroll
    for (int mi = 0; mi < 2; mi++)
#pragma unroll
        for (int ni = 0; ni < 8; ni++)
#pragma unroll
            for (int r = 0; r < 4; r++) acc[mi][ni][r] = 0.f;

    const int srow = tid >> 1;
    const int ss0  = (tid & 1) * 2;
    const __half* aS0 = Ahi + (size_t)srow * lda + ss0 * 8;
    const __half* aS1 = Alo + (size_t)srow * lda + ss0 * 8;
    const __half* wS0 = Whi + (size_t)srow * ldw + ss0 * 8;
    const __half* wS1 = Wlo + (size_t)srow * ldw + ss0 * 8;
    const uint32_t aD0 = (uint32_t)((0*128 + srow) * KSTR * 2 + ss0 * 16);
    const uint32_t aD1 = (uint32_t)((1*128 + srow) * KSTR * 2 + ss0 * 16);
    const uint32_t wD0 = (uint32_t)((2*128 + srow) * KSTR * 2 + ss0 * 16);
    const uint32_t wD1 = (uint32_t)((3*128 + srow) * KSTR * 2 + ss0 * 16);

#define G128_ISSUE(ch, buf) do { \
    const int _kt = (ch) * KC; const uint32_t _sb = smb + (buf) * ST128_BYTES; \
    CP16(_sb + aD0,      aS0 + _kt);     CP16(_sb + aD0 + 16, aS0 + _kt + 8); \
    CP16(_sb + aD1,      aS1 + _kt);     CP16(_sb + aD1 + 16, aS1 + _kt + 8); \
    CP16(_sb + wD0,      wS0 + _kt);     CP16(_sb + wD0 + 16, wS0 + _kt + 8); \
    CP16(_sb + wD1,      wS1 + _kt);     CP16(_sb + wD1 + 16, wS1 + _kt + 8); \
    CPC(); } while (0)

    const int nch = K / KC;
    G128_ISSUE(0, 0);
    if (nch > 1) G128_ISSUE(1, 1);

    for (int i = 0; i < nch; i++) {
        if (i + 1 < nch) CPW1(); else CPW0();
        __syncthreads();
        const __half* sAh = sm + (size_t)(i & 1) * ST128_HALFS;
        const __half* sAl = sAh + 128 * KSTR;
        const __half* sWh = sAl + 128 * KSTR;
        const __half* sWl = sWh + 128 * KSTR;
#pragma unroll
        for (int kq = 0; kq < KC; kq += 16) {
            uint32_t ah[2][4], al[2][4];
#pragma unroll
            for (int mi = 0; mi < 2; mi++) {
                const int base = (wm*32 + mi*16 + gr) * KSTR + kq + gc*2;
                ah[mi][0] = *(const uint32_t*)&sAh[base];
                ah[mi][1] = *(const uint32_t*)&sAh[base + 8*KSTR];
                ah[mi][2] = *(const uint32_t*)&sAh[base + 8];
                ah[mi][3] = *(const uint32_t*)&sAh[base + 8*KSTR + 8];
                al[mi][0] = *(const uint32_t*)&sAl[base];
                al[mi][1] = *(const uint32_t*)&sAl[base + 8*KSTR];
                al[mi][2] = *(const uint32_t*)&sAl[base + 8];
                al[mi][3] = *(const uint32_t*)&sAl[base + 8*KSTR + 8];
            }
#pragma unroll
            for (int ni = 0; ni < 8; ni++) {
                const int bb = (wn*64 + ni*8 + gr) * KSTR + kq + gc*2;
                uint32_t bh[2] = {*(const uint32_t*)&sWh[bb],
                                  *(const uint32_t*)&sWh[bb + 8]};
                uint32_t bl[2] = {*(const uint32_t*)&sWl[bb],
                                  *(const uint32_t*)&sWl[bb + 8]};
#pragma unroll
                for (int mi = 0; mi < 2; mi++) {
                    MMA_F16(acc[mi][ni], ah[mi], bh);
                    MMA_F16(acc[mi][ni], ah[mi], bl);
                    MMA_F16(acc[mi][ni], al[mi], bh);
                }
            }
        }
        __syncthreads();
        if (i + 2 < nch) G128_ISSUE(i + 2, i & 1);
    }
#undef G128_ISSUE

#pragma unroll
    for (int mi = 0; mi < 2; mi++) {
        const int r0 = wm*32 + mi*16 + gr;
#pragma unroll
        for (int ni = 0; ni < 8; ni++) {
            const int c = wn*64 + ni*8 + gc*2;
            float b0 = 0.f, b1 = 0.f;
            if (bias) { b0 = bias[c]; b1 = bias[c+1]; }
            float v00 = acc[mi][ni][0]*alpha + b0, v01 = acc[mi][ni][1]*alpha + b1;
            float v10 = acc[mi][ni][2]*alpha + b0, v11 = acc[mi][ni][3]*alpha + b1;
            if (relu) {
                v00 = fmaxf(v00, 0.f); v01 = fmaxf(v01, 0.f);
                v10 = fmaxf(v10, 0.f); v11 = fmaxf(v11, 0.f);
            }
            if (Cf) {
                float2 o0 = {v00, v01}, o1 = {v10, v11};
                *(float2*)(Cf + (size_t)r0 * ldc + c)       = o0;
                *(float2*)(Cf + (size_t)(r0 + 8) * ldc + c) = o1;
            }
            if (Chi) {
                __half h00 = __float2half_rn(v00), h01 = __float2half_rn(v01);
                __half h10 = __float2half_rn(v10), h11 = __float2half_rn(v11);
                *(__half2*)(Chi + (size_t)r0 * ldc + c)       = __halves2half2(h00, h01);
                *(__half2*)(Chi + (size_t)(r0 + 8) * ldc + c) = __halves2half2(h10, h11);
                __half l00 = __float2half_rn(v00 - __half2float(h00));
                __half l01 = __float2half_rn(v01 - __half2float(h01));
                __half l10 = __float2half_rn(v10 - __half2float(h10));
                __half l11 = __float2half_rn(v11 - __half2float(h11));
                *(__half2*)(Clo + (size_t)r0 * ldc + c)       = __halves2half2(l00, l01);
                *(__half2*)(Clo + (size_t)(r0 + 8) * ldc + c) = __halves2half2(l10, l11);
            }
        }
    }
}

// ========== core: 128x64 tile (ctx), split only output ======================
__device__ __forceinline__ void gemm64_core(
    const __half* __restrict__ Ahi, const __half* __restrict__ Alo, int lda,
    const __half* __restrict__ Whi, const __half* __restrict__ Wlo, int ldw,
    __half* __restrict__ Chi, __half* __restrict__ Clo, int ldc, int K)
{
    extern __shared__ __half sm[];
    const uint32_t smb = smem_u32(sm);
    const int tid = threadIdx.x;
    const int wid = tid >> 5, lane = tid & 31;
    const int wm = wid >> 1, wn = wid & 1, gr = lane >> 2, gc = lane & 3;

    float acc[2][4][4];
#pragma unroll
    for (int mi = 0; mi < 2; mi++)
#pragma unroll
        for (int ni = 0; ni < 4; ni++)
#pragma unroll
            for (int r = 0; r < 4; r++) acc[mi][ni][r] = 0.f;

    const __half* src6[6];
    uint32_t dst6[6];
#pragma unroll
    for (int j = 0; j < 6; j++) {
        const int cid = tid + j * 256;
        if (cid < 1024) {
            const int comp = cid >> 9, r = (cid >> 2) & 127, s = cid & 3;
            src6[j] = (comp ? Alo : Ahi) + (size_t)r * lda + s * 8;
            dst6[j] = (uint32_t)(((comp*128 + r) * KSTR) * 2 + s * 16);
        } else {
            const int q = cid - 1024;
            const int comp = q >> 8, r = (q >> 2) & 63, s = q & 3;
            src6[j] = (comp ? Wlo : Whi) + (size_t)r * ldw + s * 8;
            dst6[j] = (uint32_t)(((256 + comp*64 + r) * KSTR) * 2 + s * 16);
        }
    }
#define G64_ISSUE(ch, buf) do { \
    const int _kt = (ch) * KC; const uint32_t _sb = smb + (buf) * ST64_BYTES; \
    _Pragma("unroll") for (int j = 0; j < 6; j++) CP16(_sb + dst6[j], src6[j] + _kt); \
    CPC(); } while (0)

    const int nch = K / KC;
    G64_ISSUE(0, 0);
    if (nch > 1) G64_ISSUE(1, 1);

    for (int i = 0; i < nch; i++) {
        if (i + 1 < nch) CPW1(); else CPW0();
        __syncthreads();
        const __half* sAh = sm + (size_t)(i & 1) * ST64_HALFS;
        const __half* sAl = sAh + 128 * KSTR;
        const __half* sWh = sAl + 128 * KSTR;
        const __half* sWl = sWh + 64 * KSTR;
#pragma unroll
        for (int kq = 0; kq < KC; kq += 16) {
            uint32_t ah[2][4], al[2][4];
#pragma unroll
            for (int mi = 0; mi < 2; mi++) {
                const int base = (wm*32 + mi*16 + gr) * KSTR + kq + gc*2;
                ah[mi][0] = *(const uint32_t*)&sAh[base];
                ah[mi][1] = *(const uint32_t*)&sAh[base + 8*KSTR];
                ah[mi][2] = *(const uint32_t*)&sAh[base + 8];
                ah[mi][3] = *(const uint32_t*)&sAh[base + 8*KSTR + 8];
                al[mi][0] = *(const uint32_t*)&sAl[base];
                al[mi][1] = *(const uint32_t*)&sAl[base + 8*KSTR];
                al[mi][2] = *(const uint32_t*)&sAl[base + 8];
                al[mi][3] = *(const uint32_t*)&sAl[base + 8*KSTR + 8];
            }
#pragma unroll
            for (int ni = 0; ni < 4; ni++) {
                const int bb = (wn*32 + ni*8 + gr) * KSTR + kq + gc*2;
                uint32_t bh[2] = {*(const uint32_t*)&sWh[bb],
                                  *(const uint32_t*)&sWh[bb + 8]};
                uint32_t bl[2] = {*(const uint32_t*)&sWl[bb],
                                  *(const uint32_t*)&sWl[bb + 8]};
#pragma unroll
                for (int mi = 0; mi < 2; mi++) {
                    MMA_F16(acc[mi][ni], ah[mi], bh);
                    MMA_F16(acc[mi][ni], ah[mi], bl);
                    MMA_F16(acc[mi][ni], al[mi], bh);
                }
            }
        }
        __syncthreads();
        if (i + 2 < nch) G64_ISSUE(i + 2, i & 1);
    }
#undef G64_ISSUE

#pragma unroll
    for (int mi = 0; mi < 2; mi++) {
        const int r0 = wm*32 + mi*16 + gr;
#pragma unroll
        for (int ni = 0; ni < 4; ni++) {
            const int c = wn*32 + ni*8 + gc*2;
            float v00 = acc[mi][ni][0], v01 = acc[mi][ni][1];
            float v10 = acc[mi][ni][2], v11 = acc[mi][ni][3];
            __half h00 = __float2half_rn(v00), h01 = __float2half_rn(v01);
            __half h10 = __float2half_rn(v10), h11 = __float2half_rn(v11);
            *(__half2*)(Chi + (size_t)r0 * ldc + c)       = __halves2half2(h00, h01);
            *(__half2*)(Chi + (size_t)(r0 + 8) * ldc + c) = __halves2half2(h10, h11);
            __half l00 = __float2half_rn(v00 - __half2float(h00));
            __half l01 = __float2half_rn(v01 - __half2float(h01));
            __half l10 = __float2half_rn(v10 - __half2float(h10));
            __half l11 = __float2half_rn(v11 - __half2float(h11));
            *(__half2*)(Clo + (size_t)r0 * ldc + c)       = __halves2half2(l00, l01);
            *(__half2*)(Clo + (size_t)(r0 + 8) * ldc + c) = __halves2half2(l10, l11);
        }
    }
}

// ---- wrapper kernels --------------------------------------------------------
__global__ void __launch_bounds__(256, 2)
gemm_w_kernel(const __half* __restrict__ Ahi, const __half* __restrict__ Alo,
              const __half* __restrict__ Whi, const __half* __restrict__ Wlo,
              const float* __restrict__ bias,
              float* __restrict__ Cf, __half* __restrict__ Chi,
              __half* __restrict__ Clo, int K, int ldc, int relu)
{
    const size_t ao = (size_t)blockIdx.y * 128 * K;
    const size_t wo = (size_t)blockIdx.x * 128 * K;
    const size_t co = (size_t)blockIdx.y * 128 * ldc + blockIdx.x * 128;
    gemm128_core(Ahi + ao, Alo + ao, K, Whi + wo, Wlo + wo, K,
                 bias ? bias + blockIdx.x * 128 : nullptr,
                 Cf ? Cf + co : nullptr,
                 Chi ? Chi + co : nullptr, Clo ? Clo + co : nullptr,
                 ldc, K, 1.f, relu);
}

__global__ void __launch_bounds__(256, 2)
scores_kernel(const __half* __restrict__ Qhi, const __half* __restrict__ Qlo,
              const __half* __restrict__ KVhi, const __half* __restrict__ KVlo,
              float* __restrict__ S)
{
    const int z = blockIdx.z, b = z >> 4, h = z & 15;
    const size_t ao = (size_t)b * SAQ * EDIM + (size_t)blockIdx.y * 128 * EDIM + h * DH;
    const size_t wo = (size_t)b * SBK * KVSTR + (size_t)blockIdx.x * 128 * KVSTR + h * DH;
    const size_t co = (size_t)z * SAQ * SBK + (size_t)blockIdx.y * 128 * SBK + blockIdx.x * 128;
    gemm128_core(Qhi + ao, Qlo + ao, EDIM, KVhi + wo, KVlo + wo, KVSTR,
                 nullptr, S + co, nullptr, nullptr, SBK, DH, ATT_SCALE, 0);
}

__global__ void __launch_bounds__(256, 2)
ctx_kernel(const __half* __restrict__ Phi, const __half* __restrict__ Plo,
           const __half* __restrict__ VThi, const __half* __restrict__ VTlo,
           __half* __restrict__ Chi, __half* __restrict__ Clo)
{
    const int h = blockIdx.x, b = blockIdx.z;
    const int z = b * 16 + h;
    const size_t ao = (size_t)z * SAQ * SBK + (size_t)blockIdx.y * 128 * SBK;
    const size_t wo = (size_t)b * EDIM * SBK + (size_t)h * DH * SBK;
    const size_t co = ((size_t)b * SAQ + blockIdx.y * 128) * EDIM + h * DH;
    gemm64_core(Phi + ao, Plo + ao, SBK, VThi + wo, VTlo + wo, SBK,
                Chi + co, Clo + co, EDIM, SBK);
}

// ---- V transpose: sVT[b][d][k] = sKV[b][k][EDIM+d] --------------------------
__global__ void __launch_bounds__(256)
vt_kernel(const __half* __restrict__ KVhi, const __half* __restrict__ KVlo,
          __half* __restrict__ VThi, __half* __restrict__ VTlo)
{
    __shared__ __half th[32][34], tl[32][34];
    const int b = blockIdx.z;
    const int k0 = blockIdx.x * 32, d0 = blockIdx.y * 32;
    const int tx = threadIdx.x & 31, ty = threadIdx.x >> 5;
#pragma unroll
    for (int i = 0; i < 4; i++) {
        const int k = ty + i * 8;
        const size_t off = ((size_t)b * SBK + k0 + k) * KVSTR + EDIM + d0 + tx;
        th[k][tx] = KVhi[off];
        tl[k][tx] = KVlo[off];
    }
    __syncthreads();
#pragma unroll
    for (int i = 0; i < 4; i++) {
        const int d = ty + i * 8;
        const size_t off = ((size_t)b * EDIM + d0 + d) * SBK + k0 + tx;
        VThi[off] = th[tx][d];
        VTlo[off] = tl[tx][d];
    }
}

// ---------------- softmax (f32 in, split fp16 out) ---------------------------
__global__ void __launch_bounds__(128)
softmax_kernel(const float* __restrict__ S,
               __half* __restrict__ Ph, __half* __restrict__ Pl)
{
    const size_t row = blockIdx.x;
    const float* p = S + row * SBK;
    const int tid = threadIdx.x;
    __shared__ float sbuf[4];

    float4 v = ((const float4*)p)[tid];
    float m = fmaxf(fmaxf(v.x, v.y), fmaxf(v.z, v.w));
#pragma unroll
    for (int o = 16; o > 0; o >>= 1) m = fmaxf(m, __shfl_xor_sync(0xffffffffu, m, o));
    if ((tid & 31) == 0) sbuf[tid >> 5] = m;
    __syncthreads();
    m = fmaxf(fmaxf(sbuf[0], sbuf[1]), fmaxf(sbuf[2], sbuf[3]));
    __syncthreads();

    float4 e;
    e.x = expf(v.x - m); e.y = expf(v.y - m);
    e.z = expf(v.z - m); e.w = expf(v.w - m);
    float s = e.x + e.y + e.z + e.w;
#pragma unroll
    for (int o = 16; o > 0; o >>= 1) s += __shfl_xor_sync(0xffffffffu, s, o);
    if ((tid & 31) == 0) sbuf[tid >> 5] = s;
    __syncthreads();
    s = sbuf[0] + sbuf[1] + sbuf[2] + sbuf[3];
    const float inv = 1.0f / s;
    e.x *= inv; e.y *= inv; e.z *= inv; e.w *= inv;

    union { __half h[4]; uint2 u; } H, L;
    const float ev[4] = {e.x, e.y, e.z, e.w};
#pragma unroll
    for (int j = 0; j < 4; j++) {
        H.h[j] = __float2half_rn(ev[j]);
        L.h[j] = __float2half_rn(ev[j] - __half2float(H.h[j]));
    }
    ((uint2*)(Ph + row * SBK))[tid] = H.u;
    ((uint2*)(Pl + row * SBK))[tid] = L.u;
}

// ---------------- LayerNorm(residual) + split out ----------------------------
__global__ void __launch_bounds__(256)
ln_residual_kernel(const float* __restrict__ X, const float* __restrict__ R,
                   const float* __restrict__ g, const float* __restrict__ bta,
                   float* __restrict__ Y, __half* __restrict__ Yh,
                   __half* __restrict__ Yl)
{
    const int row = blockIdx.x;
    const int tid = threadIdx.x;
    __shared__ float sbuf[8];

    float4 x = ((const float4*)(X + (size_t)row * EDIM))[tid];
    float4 r = ((const float4*)(R + (size_t)row * EDIM))[tid];
    float4 v;
    v.x = x.x + r.x; v.y = x.y + r.y; v.z = x.z + r.z; v.w = x.w + r.w;

    float s = v.x + v.y + v.z + v.w;
#pragma unroll
    for (int o = 16; o > 0; o >>= 1) s += __shfl_xor_sync(0xffffffffu, s, o);
    if ((tid & 31) == 0) sbuf[tid >> 5] = s;
    __syncthreads();
    if (tid < 32) {
        float t = (tid < 8) ? sbuf[tid] : 0.f;
#pragma unroll
        for (int o = 4; o > 0; o >>= 1) t += __shfl_xor_sync(0xffffffffu, t, o);
        if (tid == 0) sbuf[0] = t;
    }
    __syncthreads();
    const float mean = sbuf[0] * (1.0f / EDIM);
    __syncthreads();

    float4 d;
    d.x = v.x - mean; d.y = v.y - mean; d.z = v.z - mean; d.w = v.w - mean;
    float sq = d.x*d.x + d.y*d.y + d.z*d.z + d.w*d.w;
#pragma unroll
    for (int o = 16; o > 0; o >>= 1) sq += __shfl_xor_sync(0xffffffffu, sq, o);
    if ((tid & 31) == 0) sbuf[tid >> 5] = sq;
    __syncthreads();
    if (tid < 32) {
        float t = (tid < 8) ? sbuf[tid] : 0.f;
#pragma unroll
        for (int o = 4; o > 0; o >>= 1) t += __shfl_xor_sync(0xffffffffu, t, o);
        if (tid == 0) sbuf[0] = t;
    }
    __syncthreads();
    const float var = sbuf[0] * (1.0f / EDIM);
    const float inv = rsqrtf(var + EPSV);

    float4 gg = ((const float4*)g)[tid];
    float4 bb = ((const float4*)bta)[tid];
    float4 o4;
    o4.x = d.x * inv * gg.x + bb.x;
    o4.y = d.y * inv * gg.y + bb.y;
    o4.z = d.z * inv * gg.z + bb.z;
    o4.w = d.w * inv * gg.w + bb.w;
    ((float4*)(Y + (size_t)row * EDIM))[tid] = o4;

    union { __half h[4]; uint2 u; } H, L;
    const float ov[4] = {o4.x, o4.y, o4.z, o4.w};
#pragma unroll
    for (int j = 0; j < 4; j++) {
        H.h[j] = __float2half_rn(ov[j]);
        L.h[j] = __float2half_rn(ov[j] - __half2float(H.h[j]));
    }
    ((uint2*)(Yh + (size_t)row * EDIM))[tid] = H.u;
    ((uint2*)(Yl + (size_t)row * EDIM))[tid] = L.u;
}

// ---------------- f32 -> split fp16 convert ----------------------------------
__global__ void convert_kernel(const float* __restrict__ s,
                               __half* __restrict__ h, __half* __restrict__ l,
                               long n4)
{
    long i = (long)blockIdx.x * blockDim.x + threadIdx.x;
    const long stride = (long)gridDim.x * blockDim.x;
    for (; i < n4; i += stride) {
        float4 v = ((const float4*)s)[i];
        union { __half a[4]; uint2 u; } H, L;
        const float vv[4] = {v.x, v.y, v.z, v.w};
#pragma unroll
        for (int j = 0; j < 4; j++) {
            H.a[j] = __float2half_rn(vv[j]);
            L.a[j] = __float2half_rn(vv[j] - __half2float(H.a[j]));
        }
        ((uint2*)h)[i] = H.u;
        ((uint2*)l)[i] = L.u;
    }
}

// ---------------- classifier + loss + labels ---------------------------------
__global__ void __launch_bounds__(128)
cls_kernel(const float* __restrict__ A, const float* __restrict__ cw,
           const float* __restrict__ cb, const int* __restrict__ mask,
           const int* __restrict__ cand, const int* __restrict__ labels,
           float* __restrict__ out_lab_f, int* __restrict__ out_lab_i,
           int write_float, float* __restrict__ partials)
{
    __shared__ float w0[EDIM];
    __shared__ float w1[EDIM];
    __shared__ float red[128];
    const int tid = threadIdx.x;
#pragma unroll
    for (int i = 0; i < EDIM / 128; i++) {
        w0[tid + i * 128] = cw[tid + i * 128];
        w1[tid + i * 128] = cw[EDIM + tid + i * 128];
    }
    __syncthreads();

    const int row = blockIdx.x * 128 + tid;
    const float* a = A + (size_t)row * EDIM;
    float e0 = cb[0], e1 = cb[1];
#pragma unroll 4
    for (int i = 0; i < EDIM; i += 4) {
        float4 av = *(const float4*)(a + i);
        e0 += av.x * w0[i] + av.y * w0[i+1] + av.z * w0[i+2] + av.w * w0[i+3];
        e1 += av.x * w1[i] + av.y * w1[i+1] + av.z * w1[i+2] + av.w * w1[i+3];
    }
    const int lab = labels[row];
    const float m = fmaxf(e0, e1);
    const float lse = m + logf(expf(e0 - m) + expf(e1 - m));
    const float logp = ((lab == 1) ? e1 : e0) - lse;
    const float ce = -logp;
    const float w = (lab == 1) ? WEIGHTV : 1.0f;
    const float valid = (mask[row] == 1) ? 1.0f : 0.0f;
    const float contrib = ce * w * valid;

    const int pred = (e1 > e0) ? 1 : 0;
    const int pl = (cand[row] == 1 && pred == 1) ? 1 : 0;
    if (write_float) out_lab_f[row] = (float)pl;
    else             out_lab_i[row] = pl;

    red[tid] = contrib;
    __syncthreads();
    for (int o = 64; o > 0; o >>= 1) {
        if (tid < o) red[tid] += red[tid + o];
        __syncthreads();
    }
    if (tid == 0) partials[2 * blockIdx.x] = red[0];
    __syncthreads();
    red[tid] = valid;
    __syncthreads();
    for (int o = 64; o > 0; o >>= 1) {
        if (tid < o) red[tid] += red[tid + o];
        __syncthreads();
    }
    if (tid == 0) partials[2 * blockIdx.x + 1] = red[0];
}

__global__ void finalize_kernel(const float* __restrict__ partials, int nblocks,
                                float* __restrict__ out_loss, int write_float)
{
    if (threadIdx.x == 0 && write_float) {
        float s = 0.f, v = 0.f;
        for (int i = 0; i < nblocks; i++) { s += partials[2*i]; v += partials[2*i+1]; }
        out_loss[0] = s / fmaxf(v, 1.0f);
    }
}

// ---------------------------- host driver -----------------------------------
extern "C" void kernel_launch(void* const* d_in, const int* in_sizes, int n_in,
                              void* d_out, int out_size)
{
    const float* enc   = (const float*)d_in[0];
    const float* desc  = (const float*)d_in[1];
    const int*   maskA = (const int*)  d_in[2];
    const int*   cand  = (const int*)  d_in[3];
    const int*   labels= (const int*)  d_in[4];
    const float* ipw   = (const float*)d_in[5];
    const float* ipb   = (const float*)d_in[6];
    const float* outw  = (const float*)d_in[7];
    const float* outb  = (const float*)d_in[8];
    const float* ln1g  = (const float*)d_in[9];
    const float* ln1b  = (const float*)d_in[10];
    const float* fw1   = (const float*)d_in[11];
    const float* fb1   = (const float*)d_in[12];
    const float* fw2   = (const float*)d_in[13];
    const float* fb2   = (const float*)d_in[14];
    const float* ln2g  = (const float*)d_in[15];
    const float* ln2b  = (const float*)d_in[16];
    const float* clsw  = (const float*)d_in[17];
    const float* clsb  = (const float*)d_in[18];

    float *pAf, *pA1f, *pOf, *pSf, *pPart;
    cudaGetSymbolAddress((void**)&pAf,  g_Af);
    cudaGetSymbolAddress((void**)&pA1f, g_A1f);
    cudaGetSymbolAddress((void**)&pOf,  g_Of);
    cudaGetSymbolAddress((void**)&pSf,  g_Sf);
    cudaGetSymbolAddress((void**)&pPart, g_partials);

    __half *wip_h, *wip_l, *wout_h, *wout_l, *wf1_h, *wf1_l, *wf2_h, *wf2_l;
    cudaGetSymbolAddress((void**)&wip_h,  g_wip_h);  cudaGetSymbolAddress((void**)&wip_l,  g_wip_l);
    cudaGetSymbolAddress((void**)&wout_h, g_wout_h); cudaGetSymbolAddress((void**)&wout_l, g_wout_l);
    cudaGetSymbolAddress((void**)&wf1_h,  g_wf1_h);  cudaGetSymbolAddress((void**)&wf1_l,  g_wf1_l);
    cudaGetSymbolAddress((void**)&wf2_h,  g_wf2_h);  cudaGetSymbolAddress((void**)&wf2_l,  g_wf2_l);

    __half *sA_h, *sA_l, *sA1_h, *sA1_l, *sD_h, *sD_l, *sQ_h, *sQ_l;
    __half *sKV_h, *sKV_l, *sC_h, *sC_l, *sH_h, *sH_l, *sP_h, *sP_l, *sVT_h, *sVT_l;
    cudaGetSymbolAddress((void**)&sA_h,  g_sA_h);   cudaGetSymbolAddress((void**)&sA_l,  g_sA_l);
    cudaGetSymbolAddress((void**)&sA1_h, g_sA1_h);  cudaGetSymbolAddress((void**)&sA1_l, g_sA1_l);
    cudaGetSymbolAddress((void**)&sD_h,  g_sD_h);   cudaGetSymbolAddress((void**)&sD_l,  g_sD_l);
    cudaGetSymbolAddress((void**)&sQ_h,  g_sQ_h);   cudaGetSymbolAddress((void**)&sQ_l,  g_sQ_l);
    cudaGetSymbolAddress((void**)&sKV_h, g_sKV_h);  cudaGetSymbolAddress((void**)&sKV_l, g_sKV_l);
    cudaGetSymbolAddress((void**)&sC_h,  g_sC_h);   cudaGetSymbolAddress((void**)&sC_l,  g_sC_l);
    cudaGetSymbolAddress((void**)&sH_h,  g_sH_h);   cudaGetSymbolAddress((void**)&sH_l,  g_sH_l);
    cudaGetSymbolAddress((void**)&sP_h,  g_sP_h);   cudaGetSymbolAddress((void**)&sP_l,  g_sP_l);
    cudaGetSymbolAddress((void**)&sVT_h, g_sVT_h);  cudaGetSymbolAddress((void**)&sVT_l, g_sVT_l);

    cudaFuncSetAttribute(gemm_w_kernel, cudaFuncAttributeMaxDynamicSharedMemorySize, 2*ST128_BYTES);
    cudaFuncSetAttribute(scores_kernel, cudaFuncAttributeMaxDynamicSharedMemorySize, 2*ST128_BYTES);
    cudaFuncSetAttribute(ctx_kernel,    cudaFuncAttributeMaxDynamicSharedMemorySize, 2*ST64_BYTES);

    cudaMemsetAsync(d_out, 0, (size_t)out_size * sizeof(float));
    cudaMemcpyAsync(pAf, enc, (size_t)NTOK * EDIM * sizeof(float),
                    cudaMemcpyDeviceToDevice);

    // pre-split conversions
    convert_kernel<<<4096, 256>>>(ipw,  wip_h,  wip_l,  (long)LL*3*EDIM*EDIM/4);
    convert_kernel<<<4096, 256>>>(outw, wout_h, wout_l, (long)LL*EDIM*EDIM/4);
    convert_kernel<<<4096, 256>>>(fw1,  wf1_h,  wf1_l,  (long)LL*FFD*EDIM/4);
    convert_kernel<<<4096, 256>>>(fw2,  wf2_h,  wf2_l,  (long)LL*EDIM*FFD/4);
    convert_kernel<<<4096, 256>>>(desc, sD_h,   sD_l,   (long)NTOK*EDIM/4);
    convert_kernel<<<4096, 256>>>(enc,  sA_h,   sA_l,   (long)NTOK*EDIM/4);

    const dim3 tb(256);
    const dim3 g_q(8, 32), g_kv(16, 32), g_f1(32, 32), g_f2(8, 32);
    const dim3 g_sc(4, 4, 128);
    const dim3 g_ctx(16, 4, 8);
    const dim3 g_vt(16, 32, 8);

    for (int l = 0; l < LL; l++) {
        const size_t wqo  = (size_t)l * 3 * EDIM * EDIM;
        const size_t wkvo = wqo + (size_t)EDIM * EDIM;
        const float* bq  = ipb + (size_t)l * 3 * EDIM;
        const float* bkv = bq + EDIM;

        gemm_w_kernel<<<g_q, tb, 2*ST128_BYTES>>>(
            sA_h, sA_l, wip_h + wqo, wip_l + wqo, bq,
            nullptr, sQ_h, sQ_l, EDIM, EDIM, 0);
        gemm_w_kernel<<<g_kv, tb, 2*ST128_BYTES>>>(
            sD_h, sD_l, wip_h + wkvo, wip_l + wkvo, bkv,
            nullptr, sKV_h, sKV_l, EDIM, KVSTR, 0);

        scores_kernel<<<g_sc, tb, 2*ST128_BYTES>>>(sQ_h, sQ_l, sKV_h, sKV_l, pSf);
        softmax_kernel<<<BB * HH * SAQ, 128>>>(pSf, sP_h, sP_l);
        vt_kernel<<<g_vt, 256>>>(sKV_h, sKV_l, sVT_h, sVT_l);
        ctx_kernel<<<g_ctx, tb, 2*ST64_BYTES>>>(sP_h, sP_l, sVT_h, sVT_l, sC_h, sC_l);

        gemm_w_kernel<<<g_q, tb, 2*ST128_BYTES>>>(
            sC_h, sC_l, wout_h + (size_t)l*EDIM*EDIM, wout_l + (size_t)l*EDIM*EDIM,
            outb + (size_t)l*EDIM, pOf, nullptr, nullptr, EDIM, EDIM, 0);

        ln_residual_kernel<<<NTOK, 256>>>(pAf, pOf, ln1g + (size_t)l*EDIM,
                                          ln1b + (size_t)l*EDIM, pA1f, sA1_h, sA1_l);

        gemm_w_kernel<<<g_f1, tb, 2*ST128_BYTES>>>(
            sA1_h, sA1_l, wf1_h + (size_t)l*FFD*EDIM, wf1_l + (size_t)l*FFD*EDIM,
            fb1 + (size_t)l*FFD, nullptr, sH_h, sH_l, EDIM, FFD, 1);
        gemm_w_kernel<<<g_f2, tb, 2*ST128_BYTES>>>(
            sH_h, sH_l, wf2_h + (size_t)l*EDIM*FFD, wf2_l + (size_t)l*EDIM*FFD,
            fb2 + (size_t)l*EDIM, pOf, nullptr, nullptr, FFD, EDIM, 0);

        ln_residual_kernel<<<NTOK, 256>>>(pA1f, pOf, ln2g + (size_t)l*EDIM,
                                          ln2b + (size_t)l*EDIM, pAf, sA_h, sA_l);
    }

    const int write_float = (out_size > NTOK) ? 1 : 0;
    const int lab_off = write_float ? (out_size - NTOK) : 0;
    float* outf = (float*)d_out;
    int*   outi = (int*)d_out;

    cls_kernel<<<NTOK / 128, 128>>>(pAf, clsw, clsb, maskA, cand, labels,
                                    outf + lab_off, outi, write_float, pPart);
    finalize_kernel<<<1, 32>>>(pPart, NTOK / 128, outf, write_float);
}